// round 1
// baseline (speedup 1.0000x reference)
#include <cuda_runtime.h>
#include <math.h>

// Problem constants
#define B_SZ 16
#define T_SZ 1024
#define D_SZ 1024
#define E_SZ 64
#define TS   (T_SZ - 1)          // 1023 timesteps
#define M_ROWS (TS * B_SZ)       // 16368
#define K1 (2 * D_SZ)            // 2048
#define N1 (4 * D_SZ)            // 4096
#define K2 N1                    // 4096
#define N2 D_SZ                  // 1024
#define K3 D_SZ                  // 1024
#define N3 E_SZ                  // 64

#define LOGITS_ELEMS (M_ROWS * E_SZ)   // 1,047,552

// Scratch (allocation-free rule: device globals)
__device__ float g_hs[M_ROWS * D_SZ];    // (t*B+b, d)  EMA states, 64 MB
__device__ float g_hid[(size_t)M_ROWS * N1]; // MLP hidden, 256 MB

// ---------------------------------------------------------------------------
// Kernel 1: per-channel EMA recurrence.
// One thread per (b, d). h_t = beta[d]*h_{t-1} + seq[b,t,d], t in [0, T-2].
// ---------------------------------------------------------------------------
__global__ void ema_kernel(const float* __restrict__ seq,
                           const float* __restrict__ beta_raw,
                           float* __restrict__ hs) {
    int idx = blockIdx.x * blockDim.x + threadIdx.x;  // 0 .. B*D-1
    if (idx >= B_SZ * D_SZ) return;
    int b = idx / D_SZ;
    int d = idx % D_SZ;
    float beta = 1.0f / (1.0f + expf(-beta_raw[d]));
    float h = 0.0f;
    const float* sp = seq + (size_t)b * T_SZ * D_SZ + d;
    float* hp = hs + (size_t)b * D_SZ + d;
#pragma unroll 4
    for (int t = 0; t < TS; ++t) {
        h = fmaf(beta, h, sp[(size_t)t * D_SZ]);
        hp[(size_t)t * (B_SZ * D_SZ)] = h;
    }
}

// ---------------------------------------------------------------------------
// Generic fp32 GEMM:  C[M,N] = epi( A[M,K] @ W[N,K]^T + bias[N] )
// EPI: 0 = none, 1 = relu, 2 = (.+bias)*scale
// Tiles: BM x BN x BK, thread tile TM x TN, 256 threads.
// N must be divisible by BN; K divisible by BK; M edge guarded.
// ---------------------------------------------------------------------------
template <int BM, int BN, int BK, int TM, int TN, int EPI>
__global__ void __launch_bounds__(256)
gemm_tn(const float* __restrict__ A, const float* __restrict__ W,
        const float* __restrict__ bias, const float* __restrict__ scale,
        float* __restrict__ C, int Mrows, int N, int K) {
    __shared__ float As[BK][BM + 4];
    __shared__ float Ws[BK][BN + 4];

    const int tid = threadIdx.x;
    const int m0 = blockIdx.y * BM;
    const int n0 = blockIdx.x * BN;
    const int tx = tid % (BN / TN);
    const int ty = tid / (BN / TN);

    float acc[TM][TN];
#pragma unroll
    for (int i = 0; i < TM; ++i)
#pragma unroll
        for (int j = 0; j < TN; ++j) acc[i][j] = 0.0f;

    for (int k0 = 0; k0 < K; k0 += BK) {
        // Load A tile (BM x BK), transposed into As[k][m]
#pragma unroll
        for (int i = tid; i < BM * BK / 4; i += 256) {
            int row = i / (BK / 4);
            int c = (i % (BK / 4)) * 4;
            float4 v = make_float4(0.f, 0.f, 0.f, 0.f);
            if (m0 + row < Mrows)
                v = *(const float4*)(A + (size_t)(m0 + row) * K + k0 + c);
            As[c + 0][row] = v.x;
            As[c + 1][row] = v.y;
            As[c + 2][row] = v.z;
            As[c + 3][row] = v.w;
        }
        // Load W tile (BN x BK), transposed into Ws[k][n]
#pragma unroll
        for (int i = tid; i < BN * BK / 4; i += 256) {
            int row = i / (BK / 4);
            int c = (i % (BK / 4)) * 4;
            float4 v = *(const float4*)(W + (size_t)(n0 + row) * K + k0 + c);
            Ws[c + 0][row] = v.x;
            Ws[c + 1][row] = v.y;
            Ws[c + 2][row] = v.z;
            Ws[c + 3][row] = v.w;
        }
        __syncthreads();

#pragma unroll
        for (int k = 0; k < BK; ++k) {
            float ar[TM], br[TN];
#pragma unroll
            for (int i = 0; i < TM; ++i) ar[i] = As[k][ty * TM + i];
#pragma unroll
            for (int j = 0; j < TN; ++j) br[j] = Ws[k][tx * TN + j];
#pragma unroll
            for (int i = 0; i < TM; ++i)
#pragma unroll
                for (int j = 0; j < TN; ++j)
                    acc[i][j] = fmaf(ar[i], br[j], acc[i][j]);
        }
        __syncthreads();
    }

    // Epilogue
#pragma unroll
    for (int i = 0; i < TM; ++i) {
        int row = m0 + ty * TM + i;
        if (row >= Mrows) continue;
#pragma unroll
        for (int j = 0; j < TN; ++j) {
            int col = n0 + tx * TN + j;
            float v = acc[i][j] + bias[col];
            if (EPI == 1) v = fmaxf(v, 0.0f);
            if (EPI == 2) v = v * scale[col];
            C[(size_t)row * N + col] = v;
        }
    }
}

// ---------------------------------------------------------------------------
// GEMM1 with concat gather: A[m, k] = (k < D) ? x[m,k] : hs[m, k-D]
// where x[m,k] = seq[b, t, k] with m = t*B + b.
// C = relu(A @ p1_w^T + p1_b), shape M x 4096.
// ---------------------------------------------------------------------------
template <int BM, int BN, int BK, int TM, int TN>
__global__ void __launch_bounds__(256)
gemm1_concat(const float* __restrict__ seq, const float* __restrict__ hs,
             const float* __restrict__ W, const float* __restrict__ bias,
             float* __restrict__ C) {
    const int N = N1, K = K1;
    __shared__ float As[BK][BM + 4];
    __shared__ float Ws[BK][BN + 4];

    const int tid = threadIdx.x;
    const int m0 = blockIdx.y * BM;
    const int n0 = blockIdx.x * BN;
    const int tx = tid % (BN / TN);
    const int ty = tid / (BN / TN);

    float acc[TM][TN];
#pragma unroll
    for (int i = 0; i < TM; ++i)
#pragma unroll
        for (int j = 0; j < TN; ++j) acc[i][j] = 0.0f;

    for (int k0 = 0; k0 < K; k0 += BK) {
        const bool in_seq = (k0 < D_SZ);  // whole BK tile is on one side (1024 % 16 == 0)
#pragma unroll
        for (int i = tid; i < BM * BK / 4; i += 256) {
            int row = i / (BK / 4);
            int c = (i % (BK / 4)) * 4;
            int m = m0 + row;
            float4 v = make_float4(0.f, 0.f, 0.f, 0.f);
            if (m < M_ROWS) {
                if (in_seq) {
                    int t = m >> 4;       // m / B
                    int b = m & 15;       // m % B
                    v = *(const float4*)(seq + ((size_t)b * T_SZ + t) * D_SZ + k0 + c);
                } else {
                    v = *(const float4*)(hs + (size_t)m * D_SZ + (k0 - D_SZ) + c);
                }
            }
            As[c + 0][row] = v.x;
            As[c + 1][row] = v.y;
            As[c + 2][row] = v.z;
            As[c + 3][row] = v.w;
        }
#pragma unroll
        for (int i = tid; i < BN * BK / 4; i += 256) {
            int row = i / (BK / 4);
            int c = (i % (BK / 4)) * 4;
            float4 v = *(const float4*)(W + (size_t)(n0 + row) * K + k0 + c);
            Ws[c + 0][row] = v.x;
            Ws[c + 1][row] = v.y;
            Ws[c + 2][row] = v.z;
            Ws[c + 3][row] = v.w;
        }
        __syncthreads();

#pragma unroll
        for (int k = 0; k < BK; ++k) {
            float ar[TM], br[TN];
#pragma unroll
            for (int i = 0; i < TM; ++i) ar[i] = As[k][ty * TM + i];
#pragma unroll
            for (int j = 0; j < TN; ++j) br[j] = Ws[k][tx * TN + j];
#pragma unroll
            for (int i = 0; i < TM; ++i)
#pragma unroll
                for (int j = 0; j < TN; ++j)
                    acc[i][j] = fmaf(ar[i], br[j], acc[i][j]);
        }
        __syncthreads();
    }

#pragma unroll
    for (int i = 0; i < TM; ++i) {
        int row = m0 + ty * TM + i;
        if (row >= M_ROWS) continue;
#pragma unroll
        for (int j = 0; j < TN; ++j) {
            int col = n0 + tx * TN + j;
            float v = fmaxf(acc[i][j] + bias[col], 0.0f);  // relu
            C[(size_t)row * N + col] = v;
        }
    }
}

// ---------------------------------------------------------------------------
// Launch
// ---------------------------------------------------------------------------
extern "C" void kernel_launch(void* const* d_in, const int* in_sizes, int n_in,
                              void* d_out, int out_size) {
    const float* seq      = (const float*)d_in[0];  // (16,1024,1024)
    const float* pi       = (const float*)d_in[1];  // (64,)
    const float* beta_raw = (const float*)d_in[2];  // (1024,)
    const float* p1_w     = (const float*)d_in[3];  // (4096,2048)
    const float* p1_b     = (const float*)d_in[4];  // (4096,)
    const float* p2_w     = (const float*)d_in[5];  // (1024,4096)
    const float* p2_b     = (const float*)d_in[6];  // (1024,)
    const float* W_w      = (const float*)d_in[7];  // (64,1024)
    const float* W_b      = (const float*)d_in[8];  // (64,)

    float* logits = (float*)d_out;                 // (1023,16,64)
    float* xhat   = (float*)d_out + LOGITS_ELEMS;  // (1023,16,1024)

    float* hs;
    float* hid;
    cudaGetSymbolAddress((void**)&hs, g_hs);
    cudaGetSymbolAddress((void**)&hid, g_hid);

    // 1) EMA scan
    ema_kernel<<<(B_SZ * D_SZ + 255) / 256, 256>>>(seq, beta_raw, hs);

    // 2) hid = relu(concat(x,hs) @ p1_w^T + p1_b)   [M x 4096]
    {
        dim3 grid(N1 / 128, (M_ROWS + 127) / 128);
        gemm1_concat<128, 128, 16, 8, 8><<<grid, 256>>>(seq, hs, p1_w, p1_b, hid);
    }

    // 3) x_hat = hid @ p2_w^T + p2_b   [M x 1024]  -> written straight into d_out
    {
        dim3 grid(N2 / 128, (M_ROWS + 127) / 128);
        gemm_tn<128, 128, 16, 8, 8, 0><<<grid, 256>>>(hid, p2_w, p2_b, nullptr,
                                                      xhat, M_ROWS, N2, K2);
    }

    // 4) logits = (x_hat @ W_w^T + W_b) * pi   [M x 64]
    {
        dim3 grid(N3 / 64, (M_ROWS + 127) / 128);
        gemm_tn<128, 64, 16, 8, 4, 2><<<grid, 256>>>(xhat, W_w, W_b, pi,
                                                     logits, M_ROWS, N3, K3);
    }
}

// round 4
// speedup vs baseline: 2.0878x; 2.0878x over previous
#include <cuda_runtime.h>
#include <cuda_bf16.h>
#include <math.h>
#include <stdint.h>

// ---------------------------------------------------------------------------
// Problem constants
// ---------------------------------------------------------------------------
#define B_SZ 16
#define T_SZ 1024
#define D_SZ 1024
#define E_SZ 64
#define TS   (T_SZ - 1)          // 1023
#define M_ROWS (TS * B_SZ)       // 16368
#define M_PAD  16384
#define K1 2048
#define N1 4096
#define K2 4096
#define N2 1024
#define K3 1024
#define N3 64
#define LOGITS_ELEMS (M_ROWS * E_SZ)

// GEMM tiling
#define BM 128
#define BN 128
#define BK 32                    // bf16 elements per k-chunk (64 bytes/row)
#define STAGES 3
#define ROW_BYTES 80             // 64B data + 16B skew -> conflict-free ldmatrix
#define ARR_BYTES (BM * ROW_BYTES)          // 10240 per array (hi or lo)
#define STAGE_BYTES (4 * ARR_BYTES)         // Ahi|Alo|Bhi|Blo = 40960
#define SMEM_TOTAL (STAGES * STAGE_BYTES)   // 122880

// ---------------------------------------------------------------------------
// Device scratch (16B aligned for cp.async / vector stores)
// ---------------------------------------------------------------------------
__device__ __align__(16) __nv_bfloat16 g_a1hi[(size_t)M_PAD * K1];
__device__ __align__(16) __nv_bfloat16 g_a1lo[(size_t)M_PAD * K1];
__device__ __align__(16) __nv_bfloat16 g_w1hi[(size_t)N1 * K1];
__device__ __align__(16) __nv_bfloat16 g_w1lo[(size_t)N1 * K1];
__device__ __align__(16) __nv_bfloat16 g_hidhi[(size_t)M_PAD * N1];
__device__ __align__(16) __nv_bfloat16 g_hidlo[(size_t)M_PAD * N1];
__device__ __align__(16) __nv_bfloat16 g_w2hi[(size_t)N2 * K2];
__device__ __align__(16) __nv_bfloat16 g_w2lo[(size_t)N2 * K2];

// ---------------------------------------------------------------------------
// PTX helpers (all base-arch: sm_80+ instructions only)
// ---------------------------------------------------------------------------
__device__ __forceinline__ uint32_t smem_u32(const void* p) {
    uint32_t a;
    asm("{ .reg .u64 t; cvta.to.shared.u64 t, %1; cvt.u32.u64 %0, t; }" : "=r"(a) : "l"(p));
    return a;
}

__device__ __forceinline__ void cp_async16(uint32_t dst, const void* src) {
    asm volatile("cp.async.cg.shared.global [%0], [%1], 16;" :: "r"(dst), "l"(src));
}
__device__ __forceinline__ void cp_commit() {
    asm volatile("cp.async.commit_group;" ::: "memory");
}
template <int N>
__device__ __forceinline__ void cp_wait() {
    asm volatile("cp.async.wait_group %0;" :: "n"(N) : "memory");
}

__device__ __forceinline__ void ldsm_x4(uint32_t* r, uint32_t addr) {
    asm volatile("ldmatrix.sync.aligned.m8n8.x4.shared.b16 {%0,%1,%2,%3}, [%4];"
                 : "=r"(r[0]), "=r"(r[1]), "=r"(r[2]), "=r"(r[3]) : "r"(addr));
}

__device__ __forceinline__ void mma_bf16(float* d, const uint32_t* a, uint32_t b0, uint32_t b1) {
    asm volatile(
        "mma.sync.aligned.m16n8k16.row.col.f32.bf16.bf16.f32 "
        "{%0,%1,%2,%3}, {%4,%5,%6,%7}, {%8,%9}, {%0,%1,%2,%3};"
        : "+f"(d[0]), "+f"(d[1]), "+f"(d[2]), "+f"(d[3])
        : "r"(a[0]), "r"(a[1]), "r"(a[2]), "r"(a[3]), "r"(b0), "r"(b1));
}

// ---------------------------------------------------------------------------
// bf16 hi/lo split
// ---------------------------------------------------------------------------
__device__ __forceinline__ void split_bf16(float v, __nv_bfloat16& hi, __nv_bfloat16& lo) {
    hi = __float2bfloat16(v);
    lo = __float2bfloat16(v - __bfloat162float(hi));
}

// ---------------------------------------------------------------------------
// Weight conversion: fp32 -> bf16 hi/lo
// ---------------------------------------------------------------------------
__global__ void conv_w_kernel(const float* __restrict__ in,
                              __nv_bfloat16* __restrict__ hi,
                              __nv_bfloat16* __restrict__ lo, size_t n4) {
    size_t i = (size_t)blockIdx.x * blockDim.x + threadIdx.x;
    if (i >= n4) return;
    float4 v = ((const float4*)in)[i];
    __nv_bfloat16 h0, l0, h1, l1, h2, l2, h3, l3;
    split_bf16(v.x, h0, l0); split_bf16(v.y, h1, l1);
    split_bf16(v.z, h2, l2); split_bf16(v.w, h3, l3);
    ((ushort4*)hi)[i] = make_ushort4(__bfloat16_as_ushort(h0), __bfloat16_as_ushort(h1),
                                     __bfloat16_as_ushort(h2), __bfloat16_as_ushort(h3));
    ((ushort4*)lo)[i] = make_ushort4(__bfloat16_as_ushort(l0), __bfloat16_as_ushort(l1),
                                     __bfloat16_as_ushort(l2), __bfloat16_as_ushort(l3));
}

// ---------------------------------------------------------------------------
// Build x-half of A1 (k < 1024 ONLY); pad rows zero BOTH halves.  m = t*16+b
// ---------------------------------------------------------------------------
__global__ void conv_x_kernel(const float* __restrict__ seq,
                              __nv_bfloat16* __restrict__ a1hi,
                              __nv_bfloat16* __restrict__ a1lo) {
    size_t i = (size_t)blockIdx.x * blockDim.x + threadIdx.x;  // over M_PAD*256
    if (i >= (size_t)M_PAD * 256) return;
    int m = (int)(i >> 8);
    int k = (int)(i & 255) * 4;              // k in [0, 1024)
    size_t o = (size_t)m * K1 + k;
    if (m < M_ROWS) {
        int t = m >> 4, b = m & 15;
        float4 v = *(const float4*)(seq + ((size_t)b * T_SZ + t) * D_SZ + k);
        __nv_bfloat16 h0, l0, h1, l1, h2, l2, h3, l3;
        split_bf16(v.x, h0, l0); split_bf16(v.y, h1, l1);
        split_bf16(v.z, h2, l2); split_bf16(v.w, h3, l3);
        *(ushort4*)(a1hi + o) = make_ushort4(__bfloat16_as_ushort(h0), __bfloat16_as_ushort(h1),
                                             __bfloat16_as_ushort(h2), __bfloat16_as_ushort(h3));
        *(ushort4*)(a1lo + o) = make_ushort4(__bfloat16_as_ushort(l0), __bfloat16_as_ushort(l1),
                                             __bfloat16_as_ushort(l2), __bfloat16_as_ushort(l3));
    } else {
        ushort4 z = make_ushort4(0, 0, 0, 0);
        *(ushort4*)(a1hi + o) = z;           // x half
        *(ushort4*)(a1lo + o) = z;
        *(ushort4*)(a1hi + o + D_SZ) = z;    // hs half (k+1024 < 2048: in-bounds)
        *(ushort4*)(a1lo + o + D_SZ) = z;
    }
}

// ---------------------------------------------------------------------------
// EMA recurrence -> A1 columns [1024,2048) as bf16 hi/lo
// ---------------------------------------------------------------------------
__global__ void ema_kernel(const float* __restrict__ seq,
                           const float* __restrict__ beta_raw,
                           __nv_bfloat16* __restrict__ a1hi,
                           __nv_bfloat16* __restrict__ a1lo) {
    int idx = blockIdx.x * blockDim.x + threadIdx.x;
    if (idx >= B_SZ * D_SZ) return;
    int b = idx / D_SZ, d = idx % D_SZ;
    float beta = 1.0f / (1.0f + expf(-beta_raw[d]));
    float h = 0.0f;
    const float* sp = seq + (size_t)b * T_SZ * D_SZ + d;
    size_t base = (size_t)b * K1 + D_SZ + d;
    for (int t = 0; t < TS; ++t) {
        h = fmaf(beta, h, sp[(size_t)t * D_SZ]);
        __nv_bfloat16 hi, lo; split_bf16(h, hi, lo);
        size_t o = base + (size_t)t * (B_SZ * K1);
        a1hi[o] = hi;
        a1lo[o] = lo;
    }
}

// ---------------------------------------------------------------------------
// Split-bf16 mma.sync GEMM: D[M_PAD,N] = (Ahi+Alo)(Whi+Wlo)^T  (3-term)
// EPI 1: relu(acc+bias) -> bf16 hi/lo        EPI 2: acc+bias -> fp32 (M_ROWS)
// 256 threads, warp grid 2(M)x4(N), warp tile 64x32, 3-stage cp.async.
// ---------------------------------------------------------------------------
template <int EPI>
__global__ void __launch_bounds__(256, 1)
gemm_split(const __nv_bfloat16* __restrict__ Ahi, const __nv_bfloat16* __restrict__ Alo,
           const __nv_bfloat16* __restrict__ Whi, const __nv_bfloat16* __restrict__ Wlo,
           const float* __restrict__ bias,
           __nv_bfloat16* __restrict__ outHi, __nv_bfloat16* __restrict__ outLo,
           float* __restrict__ outF, int N, int K) {
    extern __shared__ char smem[];
    const uint32_t sbase = smem_u32(smem);
    const int tid = threadIdx.x;
    const int lane = tid & 31;
    const int wid = tid >> 5;
    const int wm0 = (wid & 1) * 64;   // warp M offset within tile
    const int wn0 = (wid >> 1) * 32;  // warp N offset within tile
    const int m0 = blockIdx.y * BM;
    const int n0 = blockIdx.x * BN;
    const int NK = K / BK;

    float acc[4][4][4];
#pragma unroll
    for (int a = 0; a < 4; ++a)
#pragma unroll
        for (int b = 0; b < 4; ++b)
#pragma unroll
            for (int c = 0; c < 4; ++c) acc[a][b][c] = 0.0f;

    // load slots: thread covers slots tid and tid+256; slot s -> row s>>2, chunk s&3
    const int r0s = tid >> 2, c0s = tid & 3;
    const int r1s = (tid + 256) >> 2;

    auto load_stage = [&](int kc) {
        const uint32_t sb = sbase + (uint32_t)(kc % STAGES) * STAGE_BYTES;
        const size_t gcol = (size_t)kc * BK;
#pragma unroll
        for (int q = 0; q < 2; ++q) {
            const int r = q ? r1s : r0s;
            const int c = c0s;
            const uint32_t so = (uint32_t)(r * ROW_BYTES + c * 16);
            const size_t gA = (size_t)(m0 + r) * K + gcol + c * 8;
            const size_t gB = (size_t)(n0 + r) * K + gcol + c * 8;
            cp_async16(sb + so, Ahi + gA);
            cp_async16(sb + ARR_BYTES + so, Alo + gA);
            cp_async16(sb + 2 * ARR_BYTES + so, Whi + gB);
            cp_async16(sb + 3 * ARR_BYTES + so, Wlo + gB);
        }
        cp_commit();
    };

    load_stage(0);
    load_stage(1);

    const uint32_t lrow = (uint32_t)(lane & 15);
    const uint32_t lcol = (uint32_t)((lane >> 4) * 16);

    for (int kc = 0; kc < NK; ++kc) {
        if (kc + 1 < NK) cp_wait<1>(); else cp_wait<0>();
        __syncthreads();
        if (kc + 2 < NK) load_stage(kc + 2);

        const uint32_t sb = sbase + (uint32_t)(kc % STAGES) * STAGE_BYTES;
#pragma unroll
        for (int j = 0; j < 2; ++j) {   // two k16 steps
            const uint32_t colb = (uint32_t)(j * 32) + lcol;
            uint32_t ah[4][4], al[4][4];
#pragma unroll
            for (int mf = 0; mf < 4; ++mf) {
                uint32_t ad = sb + (uint32_t)((wm0 + mf * 16 + lrow) * ROW_BYTES) + colb;
                ldsm_x4(ah[mf], ad);
                ldsm_x4(al[mf], ad + ARR_BYTES);
            }
            uint32_t bh[2][4], bl[2][4];
#pragma unroll
            for (int np = 0; np < 2; ++np) {
                uint32_t bd = sb + 2 * ARR_BYTES +
                              (uint32_t)((wn0 + np * 16 + lrow) * ROW_BYTES) + colb;
                ldsm_x4(bh[np], bd);
                ldsm_x4(bl[np], bd + ARR_BYTES);
            }
#pragma unroll
            for (int mf = 0; mf < 4; ++mf) {
#pragma unroll
                for (int np = 0; np < 2; ++np) {
                    mma_bf16(acc[mf][2 * np], ah[mf], bh[np][0], bh[np][2]);
                    mma_bf16(acc[mf][2 * np], ah[mf], bl[np][0], bl[np][2]);
                    mma_bf16(acc[mf][2 * np], al[mf], bh[np][0], bh[np][2]);
                    mma_bf16(acc[mf][2 * np + 1], ah[mf], bh[np][1], bh[np][3]);
                    mma_bf16(acc[mf][2 * np + 1], ah[mf], bl[np][1], bl[np][3]);
                    mma_bf16(acc[mf][2 * np + 1], al[mf], bh[np][1], bh[np][3]);
                }
            }
        }
        __syncthreads();
    }

    // Epilogue
    const int g = lane >> 2;
    const int t2 = (lane & 3) * 2;
#pragma unroll
    for (int mf = 0; mf < 4; ++mf) {
#pragma unroll
        for (int nf = 0; nf < 4; ++nf) {
            const int n = n0 + wn0 + nf * 8 + t2;
            const float2 bv = *(const float2*)(bias + n);
#pragma unroll
            for (int h = 0; h < 2; ++h) {
                const int m = m0 + wm0 + mf * 16 + g + h * 8;
                float v0 = acc[mf][nf][h * 2 + 0] + bv.x;
                float v1 = acc[mf][nf][h * 2 + 1] + bv.y;
                if (EPI == 1) {
                    v0 = fmaxf(v0, 0.0f);
                    v1 = fmaxf(v1, 0.0f);
                    __nv_bfloat16 h0, l0, h1, l1;
                    split_bf16(v0, h0, l0);
                    split_bf16(v1, h1, l1);
                    *(ushort2*)(outHi + (size_t)m * N + n) =
                        make_ushort2(__bfloat16_as_ushort(h0), __bfloat16_as_ushort(h1));
                    *(ushort2*)(outLo + (size_t)m * N + n) =
                        make_ushort2(__bfloat16_as_ushort(l0), __bfloat16_as_ushort(l1));
                } else {
                    if (m < M_ROWS)
                        *(float2*)(outF + (size_t)m * N + n) = make_float2(v0, v1);
                }
            }
        }
    }
}

// ---------------------------------------------------------------------------
// GEMM3 (SIMT fp32): logits = (x_hat @ W_w^T + W_b) * pi
// ---------------------------------------------------------------------------
template <int TBM, int TBN, int TBK, int TM, int TN>
__global__ void __launch_bounds__(256)
gemm3_kernel(const float* __restrict__ A, const float* __restrict__ W,
             const float* __restrict__ bias, const float* __restrict__ scale,
             float* __restrict__ C, int Mrows, int N, int K) {
    __shared__ float As[TBK][TBM + 4];
    __shared__ float Ws[TBK][TBN + 4];
    const int tid = threadIdx.x;
    const int m0 = blockIdx.y * TBM;
    const int n0 = blockIdx.x * TBN;
    const int tx = tid % (TBN / TN);
    const int ty = tid / (TBN / TN);

    float acc[TM][TN];
#pragma unroll
    for (int i = 0; i < TM; ++i)
#pragma unroll
        for (int j = 0; j < TN; ++j) acc[i][j] = 0.0f;

    for (int k0 = 0; k0 < K; k0 += TBK) {
#pragma unroll
        for (int i = tid; i < TBM * TBK / 4; i += 256) {
            int row = i / (TBK / 4);
            int c = (i % (TBK / 4)) * 4;
            float4 v = make_float4(0.f, 0.f, 0.f, 0.f);
            if (m0 + row < Mrows)
                v = *(const float4*)(A + (size_t)(m0 + row) * K + k0 + c);
            As[c + 0][row] = v.x; As[c + 1][row] = v.y;
            As[c + 2][row] = v.z; As[c + 3][row] = v.w;
        }
#pragma unroll
        for (int i = tid; i < TBN * TBK / 4; i += 256) {
            int row = i / (TBK / 4);
            int c = (i % (TBK / 4)) * 4;
            float4 v = *(const float4*)(W + (size_t)(n0 + row) * K + k0 + c);
            Ws[c + 0][row] = v.x; Ws[c + 1][row] = v.y;
            Ws[c + 2][row] = v.z; Ws[c + 3][row] = v.w;
        }
        __syncthreads();
#pragma unroll
        for (int k = 0; k < TBK; ++k) {
            float ar[TM], br[TN];
#pragma unroll
            for (int i = 0; i < TM; ++i) ar[i] = As[k][ty * TM + i];
#pragma unroll
            for (int j = 0; j < TN; ++j) br[j] = Ws[k][tx * TN + j];
#pragma unroll
            for (int i = 0; i < TM; ++i)
#pragma unroll
                for (int j = 0; j < TN; ++j)
                    acc[i][j] = fmaf(ar[i], br[j], acc[i][j]);
        }
        __syncthreads();
    }
#pragma unroll
    for (int i = 0; i < TM; ++i) {
        int row = m0 + ty * TM + i;
        if (row >= Mrows) continue;
#pragma unroll
        for (int j = 0; j < TN; ++j) {
            int col = n0 + tx * TN + j;
            C[(size_t)row * N + col] = (acc[i][j] + bias[col]) * scale[col];
        }
    }
}

// ---------------------------------------------------------------------------
// Launch
// ---------------------------------------------------------------------------
extern "C" void kernel_launch(void* const* d_in, const int* in_sizes, int n_in,
                              void* d_out, int out_size) {
    const float* seq      = (const float*)d_in[0];
    const float* pi       = (const float*)d_in[1];
    const float* beta_raw = (const float*)d_in[2];
    const float* p1_w     = (const float*)d_in[3];
    const float* p1_b     = (const float*)d_in[4];
    const float* p2_w     = (const float*)d_in[5];
    const float* p2_b     = (const float*)d_in[6];
    const float* W_w      = (const float*)d_in[7];
    const float* W_b      = (const float*)d_in[8];

    float* logits = (float*)d_out;
    float* xhat   = (float*)d_out + LOGITS_ELEMS;

    __nv_bfloat16 *a1hi, *a1lo, *w1hi, *w1lo, *hidhi, *hidlo, *w2hi, *w2lo;
    cudaGetSymbolAddress((void**)&a1hi, g_a1hi);
    cudaGetSymbolAddress((void**)&a1lo, g_a1lo);
    cudaGetSymbolAddress((void**)&w1hi, g_w1hi);
    cudaGetSymbolAddress((void**)&w1lo, g_w1lo);
    cudaGetSymbolAddress((void**)&hidhi, g_hidhi);
    cudaGetSymbolAddress((void**)&hidlo, g_hidlo);
    cudaGetSymbolAddress((void**)&w2hi, g_w2hi);
    cudaGetSymbolAddress((void**)&w2lo, g_w2lo);

    cudaFuncSetAttribute(gemm_split<1>, cudaFuncAttributeMaxDynamicSharedMemorySize, SMEM_TOTAL);
    cudaFuncSetAttribute(gemm_split<2>, cudaFuncAttributeMaxDynamicSharedMemorySize, SMEM_TOTAL);

    {
        size_t n4 = (size_t)N1 * K1 / 4;
        conv_w_kernel<<<(unsigned)((n4 + 255) / 256), 256>>>(p1_w, w1hi, w1lo, n4);
    }
    {
        size_t n4 = (size_t)N2 * K2 / 4;
        conv_w_kernel<<<(unsigned)((n4 + 255) / 256), 256>>>(p2_w, w2hi, w2lo, n4);
    }
    {
        size_t n = (size_t)M_PAD * 256;
        conv_x_kernel<<<(unsigned)((n + 255) / 256), 256>>>(seq, a1hi, a1lo);
    }
    ema_kernel<<<(B_SZ * D_SZ + 255) / 256, 256>>>(seq, beta_raw, a1hi, a1lo);

    // GEMM1: hid = relu(A1 @ p1_w^T + p1_b) -> bf16 hi/lo
    {
        dim3 grid(N1 / BN, M_PAD / BM);
        gemm_split<1><<<grid, 256, SMEM_TOTAL>>>(a1hi, a1lo, w1hi, w1lo, p1_b,
                                                 hidhi, hidlo, nullptr, N1, K1);
    }
    // GEMM2: x_hat = hid @ p2_w^T + p2_b -> fp32 d_out
    {
        dim3 grid(N2 / BN, M_PAD / BM);
        gemm_split<2><<<grid, 256, SMEM_TOTAL>>>(hidhi, hidlo, w2hi, w2lo, p2_b,
                                                 nullptr, nullptr, xhat, N2, K2);
    }
    // GEMM3
    {
        dim3 grid(N3 / 64, (M_ROWS + 127) / 128);
        gemm3_kernel<128, 64, 16, 8, 4><<<grid, 256>>>(xhat, W_w, W_b, pi,
                                                       logits, M_ROWS, N3, K3);
    }
}

// round 5
// speedup vs baseline: 2.8612x; 1.3705x over previous
#include <cuda_runtime.h>
#include <cuda_fp16.h>
#include <math.h>
#include <stdint.h>

// ---------------------------------------------------------------------------
// Problem constants
// ---------------------------------------------------------------------------
#define B_SZ 16
#define T_SZ 1024
#define D_SZ 1024
#define E_SZ 64
#define TS   (T_SZ - 1)          // 1023
#define M_ROWS (TS * B_SZ)       // 16368
#define M_PAD  16384
#define K1 2048
#define N1 4096
#define K2 4096
#define N2 1024
#define K3 1024
#define N3 64
#define LOGITS_ELEMS (M_ROWS * E_SZ)

// GEMM tiling
#define BM 128
#define BN 128
#define BK 32                    // fp16 elements per k-chunk (64 bytes/row)
#define STAGES 4
#define ROW_BYTES 80             // 64B data + 16B skew -> conflict-free ldmatrix
#define ARR_BYTES (BM * ROW_BYTES)          // 10240 per array
#define STAGE_BYTES (3 * ARR_BYTES)         // Ahi|Alo|Bhi = 30720
#define SMEM_TOTAL (STAGES * STAGE_BYTES)   // 122880

// ---------------------------------------------------------------------------
// Device scratch (16B aligned)
// ---------------------------------------------------------------------------
__device__ __align__(16) __half g_a1hi[(size_t)M_PAD * K1];
__device__ __align__(16) __half g_a1lo[(size_t)M_PAD * K1];
__device__ __align__(16) __half g_w1[(size_t)N1 * K1];
__device__ __align__(16) __half g_hidhi[(size_t)M_PAD * N1];
__device__ __align__(16) __half g_hidlo[(size_t)M_PAD * N1];
__device__ __align__(16) __half g_w2[(size_t)N2 * K2];

// ---------------------------------------------------------------------------
// PTX helpers (base-arch sm_80+)
// ---------------------------------------------------------------------------
__device__ __forceinline__ uint32_t smem_u32(const void* p) {
    uint32_t a;
    asm("{ .reg .u64 t; cvta.to.shared.u64 t, %1; cvt.u32.u64 %0, t; }" : "=r"(a) : "l"(p));
    return a;
}

__device__ __forceinline__ void cp_async16(uint32_t dst, const void* src) {
    asm volatile("cp.async.cg.shared.global [%0], [%1], 16;" :: "r"(dst), "l"(src));
}
__device__ __forceinline__ void cp_commit() {
    asm volatile("cp.async.commit_group;" ::: "memory");
}
template <int N>
__device__ __forceinline__ void cp_wait() {
    asm volatile("cp.async.wait_group %0;" :: "n"(N) : "memory");
}

__device__ __forceinline__ void ldsm_x4(uint32_t* r, uint32_t addr) {
    asm volatile("ldmatrix.sync.aligned.m8n8.x4.shared.b16 {%0,%1,%2,%3}, [%4];"
                 : "=r"(r[0]), "=r"(r[1]), "=r"(r[2]), "=r"(r[3]) : "r"(addr));
}

__device__ __forceinline__ void mma_f16(float* d, const uint32_t* a, uint32_t b0, uint32_t b1) {
    asm volatile(
        "mma.sync.aligned.m16n8k16.row.col.f32.f16.f16.f32 "
        "{%0,%1,%2,%3}, {%4,%5,%6,%7}, {%8,%9}, {%0,%1,%2,%3};"
        : "+f"(d[0]), "+f"(d[1]), "+f"(d[2]), "+f"(d[3])
        : "r"(a[0]), "r"(a[1]), "r"(a[2]), "r"(a[3]), "r"(b0), "r"(b1));
}

// ---------------------------------------------------------------------------
// fp16 hi/lo split
// ---------------------------------------------------------------------------
__device__ __forceinline__ void split_h(float v, __half& hi, __half& lo) {
    hi = __float2half_rn(v);
    lo = __float2half_rn(v - __half2float(hi));
}

// ---------------------------------------------------------------------------
// Weight conversion: fp32 -> fp16 (single, round-to-nearest)
// ---------------------------------------------------------------------------
__global__ void conv_w_kernel(const float* __restrict__ in,
                              __half* __restrict__ out, size_t n4) {
    size_t i = (size_t)blockIdx.x * blockDim.x + threadIdx.x;
    if (i >= n4) return;
    float4 v = ((const float4*)in)[i];
    ((ushort4*)out)[i] = make_ushort4(
        __half_as_ushort(__float2half_rn(v.x)), __half_as_ushort(__float2half_rn(v.y)),
        __half_as_ushort(__float2half_rn(v.z)), __half_as_ushort(__float2half_rn(v.w)));
}

// ---------------------------------------------------------------------------
// Build x-half of A1 (k < 1024 only); pad rows zero BOTH halves.  m = t*16+b
// ---------------------------------------------------------------------------
__global__ void conv_x_kernel(const float* __restrict__ seq,
                              __half* __restrict__ a1hi,
                              __half* __restrict__ a1lo) {
    size_t i = (size_t)blockIdx.x * blockDim.x + threadIdx.x;  // over M_PAD*256
    if (i >= (size_t)M_PAD * 256) return;
    int m = (int)(i >> 8);
    int k = (int)(i & 255) * 4;
    size_t o = (size_t)m * K1 + k;
    if (m < M_ROWS) {
        int t = m >> 4, b = m & 15;
        float4 v = *(const float4*)(seq + ((size_t)b * T_SZ + t) * D_SZ + k);
        __half h0, l0, h1, l1, h2, l2, h3, l3;
        split_h(v.x, h0, l0); split_h(v.y, h1, l1);
        split_h(v.z, h2, l2); split_h(v.w, h3, l3);
        *(ushort4*)(a1hi + o) = make_ushort4(__half_as_ushort(h0), __half_as_ushort(h1),
                                             __half_as_ushort(h2), __half_as_ushort(h3));
        *(ushort4*)(a1lo + o) = make_ushort4(__half_as_ushort(l0), __half_as_ushort(l1),
                                             __half_as_ushort(l2), __half_as_ushort(l3));
    } else {
        ushort4 z = make_ushort4(0, 0, 0, 0);
        *(ushort4*)(a1hi + o) = z;
        *(ushort4*)(a1lo + o) = z;
        *(ushort4*)(a1hi + o + D_SZ) = z;
        *(ushort4*)(a1lo + o + D_SZ) = z;
    }
}

// ---------------------------------------------------------------------------
// EMA recurrence -> A1 columns [1024,2048) as fp16 hi/lo
// ---------------------------------------------------------------------------
__global__ void ema_kernel(const float* __restrict__ seq,
                           const float* __restrict__ beta_raw,
                           __half* __restrict__ a1hi,
                           __half* __restrict__ a1lo) {
    int idx = blockIdx.x * blockDim.x + threadIdx.x;
    if (idx >= B_SZ * D_SZ) return;
    int b = idx / D_SZ, d = idx % D_SZ;
    float beta = 1.0f / (1.0f + expf(-beta_raw[d]));
    float h = 0.0f;
    const float* sp = seq + (size_t)b * T_SZ * D_SZ + d;
    size_t base = (size_t)b * K1 + D_SZ + d;
    for (int t = 0; t < TS; ++t) {
        h = fmaf(beta, h, sp[(size_t)t * D_SZ]);
        __half hi, lo; split_h(h, hi, lo);
        size_t o = base + (size_t)t * (B_SZ * K1);
        a1hi[o] = hi;
        a1lo[o] = lo;
    }
}

// ---------------------------------------------------------------------------
// 2-term fp16 mma.sync GEMM: D[M_PAD,N] = (Ahi+Alo) @ Wh^T    (fp32 acc)
// EPI 1: relu(acc+bias) -> fp16 hi/lo        EPI 2: acc+bias -> fp32 (M_ROWS)
// 256 threads, warps 2(M)x4(N), warp tile 64x32, 4-stage cp.async,
// ONE __syncthreads per k-chunk.
// ---------------------------------------------------------------------------
template <int EPI>
__global__ void __launch_bounds__(256, 1)
gemm_split(const __half* __restrict__ Ahi, const __half* __restrict__ Alo,
           const __half* __restrict__ Wh,
           const float* __restrict__ bias,
           __half* __restrict__ outHi, __half* __restrict__ outLo,
           float* __restrict__ outF, int N, int K) {
    extern __shared__ char smem[];
    const uint32_t sbase = smem_u32(smem);
    const int tid = threadIdx.x;
    const int lane = tid & 31;
    const int wid = tid >> 5;
    const int wm0 = (wid & 1) * 64;
    const int wn0 = (wid >> 1) * 32;
    const int m0 = blockIdx.y * BM;
    const int n0 = blockIdx.x * BN;
    const int NK = K / BK;

    float acc[4][4][4];
#pragma unroll
    for (int a = 0; a < 4; ++a)
#pragma unroll
        for (int b = 0; b < 4; ++b)
#pragma unroll
            for (int c = 0; c < 4; ++c) acc[a][b][c] = 0.0f;

    // load slots: thread covers slots tid and tid+256; slot s -> row s>>2, chunk s&3
    const int r0s = tid >> 2, c0s = tid & 3;
    const int r1s = (tid + 256) >> 2;

    auto load_stage = [&](int kc) {
        const uint32_t sb = sbase + (uint32_t)(kc % STAGES) * STAGE_BYTES;
        const size_t gcol = (size_t)kc * BK;
#pragma unroll
        for (int q = 0; q < 2; ++q) {
            const int r = q ? r1s : r0s;
            const uint32_t so = (uint32_t)(r * ROW_BYTES + c0s * 16);
            const size_t gA = (size_t)(m0 + r) * K + gcol + c0s * 8;
            const size_t gB = (size_t)(n0 + r) * K + gcol + c0s * 8;
            cp_async16(sb + so, Ahi + gA);
            cp_async16(sb + ARR_BYTES + so, Alo + gA);
            cp_async16(sb + 2 * ARR_BYTES + so, Wh + gB);
        }
        cp_commit();
    };

    load_stage(0);
    load_stage(1);
    load_stage(2);

    const uint32_t lrow = (uint32_t)(lane & 15);
    const uint32_t lcol = (uint32_t)((lane >> 4) * 16);

    for (int kc = 0; kc < NK; ++kc) {
        const int rem = NK - 1 - kc;
        if (rem >= 2) cp_wait<2>();
        else if (rem == 1) cp_wait<1>();
        else cp_wait<0>();
        __syncthreads();               // single barrier per chunk
        if (kc + 3 < NK) load_stage(kc + 3);

        const uint32_t sb = sbase + (uint32_t)(kc % STAGES) * STAGE_BYTES;
#pragma unroll
        for (int j = 0; j < 2; ++j) {   // two k16 steps
            const uint32_t colb = (uint32_t)(j * 32) + lcol;
            uint32_t ah[4][4], al[4][4];
#pragma unroll
            for (int mf = 0; mf < 4; ++mf) {
                uint32_t ad = sb + (uint32_t)((wm0 + mf * 16 + lrow) * ROW_BYTES) + colb;
                ldsm_x4(ah[mf], ad);
                ldsm_x4(al[mf], ad + ARR_BYTES);
            }
            uint32_t bh[2][4];
#pragma unroll
            for (int np = 0; np < 2; ++np) {
                uint32_t bd = sb + 2 * ARR_BYTES +
                              (uint32_t)((wn0 + np * 16 + lrow) * ROW_BYTES) + colb;
                ldsm_x4(bh[np], bd);
            }
#pragma unroll
            for (int mf = 0; mf < 4; ++mf) {
#pragma unroll
                for (int np = 0; np < 2; ++np) {
                    mma_f16(acc[mf][2 * np],     ah[mf], bh[np][0], bh[np][2]);
                    mma_f16(acc[mf][2 * np],     al[mf], bh[np][0], bh[np][2]);
                    mma_f16(acc[mf][2 * np + 1], ah[mf], bh[np][1], bh[np][3]);
                    mma_f16(acc[mf][2 * np + 1], al[mf], bh[np][1], bh[np][3]);
                }
            }
        }
    }

    // Epilogue
    const int g = lane >> 2;
    const int t2 = (lane & 3) * 2;
#pragma unroll
    for (int mf = 0; mf < 4; ++mf) {
#pragma unroll
        for (int nf = 0; nf < 4; ++nf) {
            const int n = n0 + wn0 + nf * 8 + t2;
            const float2 bv = *(const float2*)(bias + n);
#pragma unroll
            for (int h = 0; h < 2; ++h) {
                const int m = m0 + wm0 + mf * 16 + g + h * 8;
                float v0 = acc[mf][nf][h * 2 + 0] + bv.x;
                float v1 = acc[mf][nf][h * 2 + 1] + bv.y;
                if (EPI == 1) {
                    v0 = fmaxf(v0, 0.0f);
                    v1 = fmaxf(v1, 0.0f);
                    __half h0, l0, h1, l1;
                    split_h(v0, h0, l0);
                    split_h(v1, h1, l1);
                    *(ushort2*)(outHi + (size_t)m * N + n) =
                        make_ushort2(__half_as_ushort(h0), __half_as_ushort(h1));
                    *(ushort2*)(outLo + (size_t)m * N + n) =
                        make_ushort2(__half_as_ushort(l0), __half_as_ushort(l1));
                } else {
                    if (m < M_ROWS)
                        *(float2*)(outF + (size_t)m * N + n) = make_float2(v0, v1);
                }
            }
        }
    }
}

// ---------------------------------------------------------------------------
// GEMM3 (SIMT fp32): logits = (x_hat @ W_w^T + W_b) * pi
// ---------------------------------------------------------------------------
template <int TBM, int TBN, int TBK, int TM, int TN>
__global__ void __launch_bounds__(256)
gemm3_kernel(const float* __restrict__ A, const float* __restrict__ W,
             const float* __restrict__ bias, const float* __restrict__ scale,
             float* __restrict__ C, int Mrows, int N, int K) {
    __shared__ float As[TBK][TBM + 4];
    __shared__ float Ws[TBK][TBN + 4];
    const int tid = threadIdx.x;
    const int m0 = blockIdx.y * TBM;
    const int n0 = blockIdx.x * TBN;
    const int tx = tid % (TBN / TN);
    const int ty = tid / (TBN / TN);

    float acc[TM][TN];
#pragma unroll
    for (int i = 0; i < TM; ++i)
#pragma unroll
        for (int j = 0; j < TN; ++j) acc[i][j] = 0.0f;

    for (int k0 = 0; k0 < K; k0 += TBK) {
#pragma unroll
        for (int i = tid; i < TBM * TBK / 4; i += 256) {
            int row = i / (TBK / 4);
            int c = (i % (TBK / 4)) * 4;
            float4 v = make_float4(0.f, 0.f, 0.f, 0.f);
            if (m0 + row < Mrows)
                v = *(const float4*)(A + (size_t)(m0 + row) * K + k0 + c);
            As[c + 0][row] = v.x; As[c + 1][row] = v.y;
            As[c + 2][row] = v.z; As[c + 3][row] = v.w;
        }
#pragma unroll
        for (int i = tid; i < TBN * TBK / 4; i += 256) {
            int row = i / (TBK / 4);
            int c = (i % (TBK / 4)) * 4;
            float4 v = *(const float4*)(W + (size_t)(n0 + row) * K + k0 + c);
            Ws[c + 0][row] = v.x; Ws[c + 1][row] = v.y;
            Ws[c + 2][row] = v.z; Ws[c + 3][row] = v.w;
        }
        __syncthreads();
#pragma unroll
        for (int k = 0; k < TBK; ++k) {
            float ar[TM], br[TN];
#pragma unroll
            for (int i = 0; i < TM; ++i) ar[i] = As[k][ty * TM + i];
#pragma unroll
            for (int j = 0; j < TN; ++j) br[j] = Ws[k][tx * TN + j];
#pragma unroll
            for (int i = 0; i < TM; ++i)
#pragma unroll
                for (int j = 0; j < TN; ++j)
                    acc[i][j] = fmaf(ar[i], br[j], acc[i][j]);
        }
        __syncthreads();
    }
#pragma unroll
    for (int i = 0; i < TM; ++i) {
        int row = m0 + ty * TM + i;
        if (row >= Mrows) continue;
#pragma unroll
        for (int j = 0; j < TN; ++j) {
            int col = n0 + tx * TN + j;
            C[(size_t)row * N + col] = (acc[i][j] + bias[col]) * scale[col];
        }
    }
}

// ---------------------------------------------------------------------------
// Launch
// ---------------------------------------------------------------------------
extern "C" void kernel_launch(void* const* d_in, const int* in_sizes, int n_in,
                              void* d_out, int out_size) {
    const float* seq      = (const float*)d_in[0];
    const float* pi       = (const float*)d_in[1];
    const float* beta_raw = (const float*)d_in[2];
    const float* p1_w     = (const float*)d_in[3];
    const float* p1_b     = (const float*)d_in[4];
    const float* p2_w     = (const float*)d_in[5];
    const float* p2_b     = (const float*)d_in[6];
    const float* W_w      = (const float*)d_in[7];
    const float* W_b      = (const float*)d_in[8];

    float* logits = (float*)d_out;
    float* xhat   = (float*)d_out + LOGITS_ELEMS;

    __half *a1hi, *a1lo, *w1, *hidhi, *hidlo, *w2;
    cudaGetSymbolAddress((void**)&a1hi, g_a1hi);
    cudaGetSymbolAddress((void**)&a1lo, g_a1lo);
    cudaGetSymbolAddress((void**)&w1, g_w1);
    cudaGetSymbolAddress((void**)&hidhi, g_hidhi);
    cudaGetSymbolAddress((void**)&hidlo, g_hidlo);
    cudaGetSymbolAddress((void**)&w2, g_w2);

    cudaFuncSetAttribute(gemm_split<1>, cudaFuncAttributeMaxDynamicSharedMemorySize, SMEM_TOTAL);
    cudaFuncSetAttribute(gemm_split<2>, cudaFuncAttributeMaxDynamicSharedMemorySize, SMEM_TOTAL);

    {
        size_t n4 = (size_t)N1 * K1 / 4;
        conv_w_kernel<<<(unsigned)((n4 + 255) / 256), 256>>>(p1_w, w1, n4);
    }
    {
        size_t n4 = (size_t)N2 * K2 / 4;
        conv_w_kernel<<<(unsigned)((n4 + 255) / 256), 256>>>(p2_w, w2, n4);
    }
    {
        size_t n = (size_t)M_PAD * 256;
        conv_x_kernel<<<(unsigned)((n + 255) / 256), 256>>>(seq, a1hi, a1lo);
    }
    ema_kernel<<<(B_SZ * D_SZ + 255) / 256, 256>>>(seq, beta_raw, a1hi, a1lo);

    // GEMM1: hid = relu(A1 @ p1_w^T + p1_b) -> fp16 hi/lo
    {
        dim3 grid(N1 / BN, M_PAD / BM);
        gemm_split<1><<<grid, 256, SMEM_TOTAL>>>(a1hi, a1lo, w1, p1_b,
                                                 hidhi, hidlo, nullptr, N1, K1);
    }
    // GEMM2: x_hat = hid @ p2_w^T + p2_b -> fp32 d_out
    {
        dim3 grid(N2 / BN, M_PAD / BM);
        gemm_split<2><<<grid, 256, SMEM_TOTAL>>>(hidhi, hidlo, w2, p2_b,
                                                 nullptr, nullptr, xhat, N2, K2);
    }
    // GEMM3
    {
        dim3 grid(N3 / 64, (M_ROWS + 127) / 128);
        gemm3_kernel<128, 64, 16, 8, 4><<<grid, 256>>>(xhat, W_w, W_b, pi,
                                                       logits, M_ROWS, N3, K3);
    }
}

// round 6
// speedup vs baseline: 3.5034x; 1.2244x over previous
#include <cuda_runtime.h>
#include <cuda_fp16.h>
#include <math.h>
#include <stdint.h>

// ---------------------------------------------------------------------------
// Problem constants
// ---------------------------------------------------------------------------
#define B_SZ 16
#define T_SZ 1024
#define D_SZ 1024
#define E_SZ 64
#define TS   (T_SZ - 1)          // 1023
#define M_ROWS (TS * B_SZ)       // 16368
#define M_PAD  16384
#define K1 2048
#define N1 4096
#define K2 4096
#define N2 1024
#define K3 1024
#define N3 64
#define LOGITS_ELEMS (M_ROWS * E_SZ)

// GEMM tiling
#define BM 128
#define BN 128
#define BK 32                    // fp16 elements per k-chunk (64 bytes/row)
#define STAGES 4
#define ROW_BYTES 80             // 64B data + 16B skew -> conflict-free ldmatrix
#define ARR_BYTES (BM * ROW_BYTES)          // 10240 per array

// ---------------------------------------------------------------------------
// Device scratch (16B aligned)
// ---------------------------------------------------------------------------
__device__ __align__(16) __half g_a1hi[(size_t)M_PAD * K1];
__device__ __align__(16) __half g_a1lo[(size_t)M_PAD * K1];
__device__ __align__(16) __half g_w1[(size_t)N1 * K1];
__device__ __align__(16) __half g_hid[(size_t)M_PAD * N1];
__device__ __align__(16) __half g_w2[(size_t)N2 * K2];

// ---------------------------------------------------------------------------
// PTX helpers (base-arch sm_80+)
// ---------------------------------------------------------------------------
__device__ __forceinline__ uint32_t smem_u32(const void* p) {
    uint32_t a;
    asm("{ .reg .u64 t; cvta.to.shared.u64 t, %1; cvt.u32.u64 %0, t; }" : "=r"(a) : "l"(p));
    return a;
}

__device__ __forceinline__ void cp_async16(uint32_t dst, const void* src) {
    asm volatile("cp.async.cg.shared.global [%0], [%1], 16;" :: "r"(dst), "l"(src));
}
__device__ __forceinline__ void cp_commit() {
    asm volatile("cp.async.commit_group;" ::: "memory");
}
template <int N>
__device__ __forceinline__ void cp_wait() {
    asm volatile("cp.async.wait_group %0;" :: "n"(N) : "memory");
}

__device__ __forceinline__ void ldsm_x4(uint32_t* r, uint32_t addr) {
    asm volatile("ldmatrix.sync.aligned.m8n8.x4.shared.b16 {%0,%1,%2,%3}, [%4];"
                 : "=r"(r[0]), "=r"(r[1]), "=r"(r[2]), "=r"(r[3]) : "r"(addr));
}

__device__ __forceinline__ void mma_f16(float* d, const uint32_t* a, uint32_t b0, uint32_t b1) {
    asm volatile(
        "mma.sync.aligned.m16n8k16.row.col.f32.f16.f16.f32 "
        "{%0,%1,%2,%3}, {%4,%5,%6,%7}, {%8,%9}, {%0,%1,%2,%3};"
        : "+f"(d[0]), "+f"(d[1]), "+f"(d[2]), "+f"(d[3])
        : "r"(a[0]), "r"(a[1]), "r"(a[2]), "r"(a[3]), "r"(b0), "r"(b1));
}

// ---------------------------------------------------------------------------
// fp16 hi/lo split
// ---------------------------------------------------------------------------
__device__ __forceinline__ void split_h(float v, __half& hi, __half& lo) {
    hi = __float2half_rn(v);
    lo = __float2half_rn(v - __half2float(hi));
}

// ---------------------------------------------------------------------------
// Weight conversion: fp32 -> fp16
// ---------------------------------------------------------------------------
__global__ void conv_w_kernel(const float* __restrict__ in,
                              __half* __restrict__ out, size_t n4) {
    size_t i = (size_t)blockIdx.x * blockDim.x + threadIdx.x;
    if (i >= n4) return;
    float4 v = ((const float4*)in)[i];
    ((ushort4*)out)[i] = make_ushort4(
        __half_as_ushort(__float2half_rn(v.x)), __half_as_ushort(__float2half_rn(v.y)),
        __half_as_ushort(__float2half_rn(v.z)), __half_as_ushort(__float2half_rn(v.w)));
}

// ---------------------------------------------------------------------------
// Build x-half of A1 (k < 1024 only); pad rows zero BOTH halves.  m = t*16+b
// ---------------------------------------------------------------------------
__global__ void conv_x_kernel(const float* __restrict__ seq,
                              __half* __restrict__ a1hi,
                              __half* __restrict__ a1lo) {
    size_t i = (size_t)blockIdx.x * blockDim.x + threadIdx.x;  // over M_PAD*256
    if (i >= (size_t)M_PAD * 256) return;
    int m = (int)(i >> 8);
    int k = (int)(i & 255) * 4;
    size_t o = (size_t)m * K1 + k;
    if (m < M_ROWS) {
        int t = m >> 4, b = m & 15;
        float4 v = *(const float4*)(seq + ((size_t)b * T_SZ + t) * D_SZ + k);
        __half h0, l0, h1, l1, h2, l2, h3, l3;
        split_h(v.x, h0, l0); split_h(v.y, h1, l1);
        split_h(v.z, h2, l2); split_h(v.w, h3, l3);
        *(ushort4*)(a1hi + o) = make_ushort4(__half_as_ushort(h0), __half_as_ushort(h1),
                                             __half_as_ushort(h2), __half_as_ushort(h3));
        *(ushort4*)(a1lo + o) = make_ushort4(__half_as_ushort(l0), __half_as_ushort(l1),
                                             __half_as_ushort(l2), __half_as_ushort(l3));
    } else {
        ushort4 z = make_ushort4(0, 0, 0, 0);
        *(ushort4*)(a1hi + o) = z;
        *(ushort4*)(a1lo + o) = z;
        *(ushort4*)(a1hi + o + D_SZ) = z;
        *(ushort4*)(a1lo + o + D_SZ) = z;
    }
}

// ---------------------------------------------------------------------------
// EMA recurrence -> A1 columns [1024,2048) as fp16 hi/lo
// ---------------------------------------------------------------------------
__global__ void ema_kernel(const float* __restrict__ seq,
                           const float* __restrict__ beta_raw,
                           __half* __restrict__ a1hi,
                           __half* __restrict__ a1lo) {
    int idx = blockIdx.x * blockDim.x + threadIdx.x;
    if (idx >= B_SZ * D_SZ) return;
    int b = idx / D_SZ, d = idx % D_SZ;
    float beta = 1.0f / (1.0f + expf(-beta_raw[d]));
    float h = 0.0f;
    const float* sp = seq + (size_t)b * T_SZ * D_SZ + d;
    size_t base = (size_t)b * K1 + D_SZ + d;
    for (int t = 0; t < TS; ++t) {
        h = fmaf(beta, h, sp[(size_t)t * D_SZ]);
        __half hi, lo; split_h(h, hi, lo);
        size_t o = base + (size_t)t * (B_SZ * K1);
        a1hi[o] = hi;
        a1lo[o] = lo;
    }
}

// ---------------------------------------------------------------------------
// fp16 mma.sync GEMM, TERMS-term A split: D = (Ahi[+Alo]) @ Wh^T  (fp32 acc)
// EPI 1: relu(acc+bias) -> fp16 out          EPI 2: acc+bias -> fp32 (M_ROWS)
// 256 threads, warps 2(M)x4(N), warp tile 64x32, 4-stage cp.async,
// one __syncthreads per k-chunk; hi/lo MMA phases separated to break
// accumulator RAW chains.
// ---------------------------------------------------------------------------
template <int EPI, int TERMS>
__global__ void __launch_bounds__(256, 1)
gemm_split(const __half* __restrict__ Ahi, const __half* __restrict__ Alo,
           const __half* __restrict__ Wh,
           const float* __restrict__ bias,
           __half* __restrict__ outH, float* __restrict__ outF, int N, int K) {
    constexpr int NARR = TERMS + 1;                 // A(,Alo),B arrays per stage
    constexpr uint32_t STB = NARR * ARR_BYTES;      // stage bytes
    constexpr uint32_t BOFF = TERMS * ARR_BYTES;    // B array offset in stage

    extern __shared__ char smem[];
    const uint32_t sbase = smem_u32(smem);
    const int tid = threadIdx.x;
    const int lane = tid & 31;
    const int wid = tid >> 5;
    const int wm0 = (wid & 1) * 64;
    const int wn0 = (wid >> 1) * 32;
    const int m0 = blockIdx.y * BM;
    const int n0 = blockIdx.x * BN;
    const int NK = K / BK;

    float acc[4][4][4];
#pragma unroll
    for (int a = 0; a < 4; ++a)
#pragma unroll
        for (int b = 0; b < 4; ++b)
#pragma unroll
            for (int c = 0; c < 4; ++c) acc[a][b][c] = 0.0f;

    const int r0s = tid >> 2, c0s = tid & 3;
    const int r1s = (tid + 256) >> 2;

    auto load_stage = [&](int kc) {
        const uint32_t sb = sbase + (uint32_t)(kc % STAGES) * STB;
        const size_t gcol = (size_t)kc * BK;
#pragma unroll
        for (int q = 0; q < 2; ++q) {
            const int r = q ? r1s : r0s;
            const uint32_t so = (uint32_t)(r * ROW_BYTES + c0s * 16);
            const size_t gA = (size_t)(m0 + r) * K + gcol + c0s * 8;
            const size_t gB = (size_t)(n0 + r) * K + gcol + c0s * 8;
            cp_async16(sb + so, Ahi + gA);
            if (TERMS == 2) cp_async16(sb + ARR_BYTES + so, Alo + gA);
            cp_async16(sb + BOFF + so, Wh + gB);
        }
        cp_commit();
    };

    load_stage(0);
    load_stage(1);
    load_stage(2);

    const uint32_t lrow = (uint32_t)(lane & 15);
    const uint32_t lcol = (uint32_t)((lane >> 4) * 16);

    for (int kc = 0; kc < NK; ++kc) {
        const int rem = NK - 1 - kc;
        if (rem >= 2) cp_wait<2>();
        else if (rem == 1) cp_wait<1>();
        else cp_wait<0>();
        __syncthreads();
        if (kc + 3 < NK) load_stage(kc + 3);

        const uint32_t sb = sbase + (uint32_t)(kc % STAGES) * STB;
#pragma unroll
        for (int j = 0; j < 2; ++j) {   // two k16 steps
            const uint32_t colb = (uint32_t)(j * 32) + lcol;
            uint32_t ah[4][4], al[4][4];
#pragma unroll
            for (int mf = 0; mf < 4; ++mf) {
                uint32_t ad = sb + (uint32_t)((wm0 + mf * 16 + lrow) * ROW_BYTES) + colb;
                ldsm_x4(ah[mf], ad);
                if (TERMS == 2) ldsm_x4(al[mf], ad + ARR_BYTES);
            }
            uint32_t bh[2][4];
#pragma unroll
            for (int np = 0; np < 2; ++np) {
                uint32_t bd = sb + BOFF +
                              (uint32_t)((wn0 + np * 16 + lrow) * ROW_BYTES) + colb;
                ldsm_x4(bh[np], bd);
            }
            // Phase 1: all hi-term MMAs (16 independent accumulators)
#pragma unroll
            for (int mf = 0; mf < 4; ++mf) {
#pragma unroll
                for (int np = 0; np < 2; ++np) {
                    mma_f16(acc[mf][2 * np],     ah[mf], bh[np][0], bh[np][2]);
                    mma_f16(acc[mf][2 * np + 1], ah[mf], bh[np][1], bh[np][3]);
                }
            }
            // Phase 2: all lo-term MMAs (reuse distance 16 from phase 1)
            if (TERMS == 2) {
#pragma unroll
                for (int mf = 0; mf < 4; ++mf) {
#pragma unroll
                    for (int np = 0; np < 2; ++np) {
                        mma_f16(acc[mf][2 * np],     al[mf], bh[np][0], bh[np][2]);
                        mma_f16(acc[mf][2 * np + 1], al[mf], bh[np][1], bh[np][3]);
                    }
                }
            }
        }
    }

    // Epilogue
    const int g = lane >> 2;
    const int t2 = (lane & 3) * 2;
#pragma unroll
    for (int mf = 0; mf < 4; ++mf) {
#pragma unroll
        for (int nf = 0; nf < 4; ++nf) {
            const int n = n0 + wn0 + nf * 8 + t2;
            const float2 bv = *(const float2*)(bias + n);
#pragma unroll
            for (int h = 0; h < 2; ++h) {
                const int m = m0 + wm0 + mf * 16 + g + h * 8;
                float v0 = acc[mf][nf][h * 2 + 0] + bv.x;
                float v1 = acc[mf][nf][h * 2 + 1] + bv.y;
                if (EPI == 1) {
                    v0 = fmaxf(v0, 0.0f);
                    v1 = fmaxf(v1, 0.0f);
                    *(ushort2*)(outH + (size_t)m * N + n) =
                        make_ushort2(__half_as_ushort(__float2half_rn(v0)),
                                     __half_as_ushort(__float2half_rn(v1)));
                } else {
                    if (m < M_ROWS)
                        *(float2*)(outF + (size_t)m * N + n) = make_float2(v0, v1);
                }
            }
        }
    }
}

// ---------------------------------------------------------------------------
// GEMM3 (SIMT fp32): logits = (x_hat @ W_w^T + W_b) * pi
// ---------------------------------------------------------------------------
template <int TBM, int TBN, int TBK, int TM, int TN>
__global__ void __launch_bounds__(256)
gemm3_kernel(const float* __restrict__ A, const float* __restrict__ W,
             const float* __restrict__ bias, const float* __restrict__ scale,
             float* __restrict__ C, int Mrows, int N, int K) {
    __shared__ float As[TBK][TBM + 4];
    __shared__ float Ws[TBK][TBN + 4];
    const int tid = threadIdx.x;
    const int m0 = blockIdx.y * TBM;
    const int n0 = blockIdx.x * TBN;
    const int tx = tid % (TBN / TN);
    const int ty = tid / (TBN / TN);

    float acc[TM][TN];
#pragma unroll
    for (int i = 0; i < TM; ++i)
#pragma unroll
        for (int j = 0; j < TN; ++j) acc[i][j] = 0.0f;

    for (int k0 = 0; k0 < K; k0 += TBK) {
#pragma unroll
        for (int i = tid; i < TBM * TBK / 4; i += 256) {
            int row = i / (TBK / 4);
            int c = (i % (TBK / 4)) * 4;
            float4 v = make_float4(0.f, 0.f, 0.f, 0.f);
            if (m0 + row < Mrows)
                v = *(const float4*)(A + (size_t)(m0 + row) * K + k0 + c);
            As[c + 0][row] = v.x; As[c + 1][row] = v.y;
            As[c + 2][row] = v.z; As[c + 3][row] = v.w;
        }
#pragma unroll
        for (int i = tid; i < TBN * TBK / 4; i += 256) {
            int row = i / (TBK / 4);
            int c = (i % (TBK / 4)) * 4;
            float4 v = *(const float4*)(W + (size_t)(n0 + row) * K + k0 + c);
            Ws[c + 0][row] = v.x; Ws[c + 1][row] = v.y;
            Ws[c + 2][row] = v.z; Ws[c + 3][row] = v.w;
        }
        __syncthreads();
#pragma unroll
        for (int k = 0; k < TBK; ++k) {
            float ar[TM], br[TN];
#pragma unroll
            for (int i = 0; i < TM; ++i) ar[i] = As[k][ty * TM + i];
#pragma unroll
            for (int j = 0; j < TN; ++j) br[j] = Ws[k][tx * TN + j];
#pragma unroll
            for (int i = 0; i < TM; ++i)
#pragma unroll
                for (int j = 0; j < TN; ++j)
                    acc[i][j] = fmaf(ar[i], br[j], acc[i][j]);
        }
        __syncthreads();
    }
#pragma unroll
    for (int i = 0; i < TM; ++i) {
        int row = m0 + ty * TM + i;
        if (row >= Mrows) continue;
#pragma unroll
        for (int j = 0; j < TN; ++j) {
            int col = n0 + tx * TN + j;
            C[(size_t)row * N + col] = (acc[i][j] + bias[col]) * scale[col];
        }
    }
}

// ---------------------------------------------------------------------------
// Launch
// ---------------------------------------------------------------------------
extern "C" void kernel_launch(void* const* d_in, const int* in_sizes, int n_in,
                              void* d_out, int out_size) {
    const float* seq      = (const float*)d_in[0];
    const float* pi       = (const float*)d_in[1];
    const float* beta_raw = (const float*)d_in[2];
    const float* p1_w     = (const float*)d_in[3];
    const float* p1_b     = (const float*)d_in[4];
    const float* p2_w     = (const float*)d_in[5];
    const float* p2_b     = (const float*)d_in[6];
    const float* W_w      = (const float*)d_in[7];
    const float* W_b      = (const float*)d_in[8];

    float* logits = (float*)d_out;
    float* xhat   = (float*)d_out + LOGITS_ELEMS;

    __half *a1hi, *a1lo, *w1, *hid, *w2;
    cudaGetSymbolAddress((void**)&a1hi, g_a1hi);
    cudaGetSymbolAddress((void**)&a1lo, g_a1lo);
    cudaGetSymbolAddress((void**)&w1, g_w1);
    cudaGetSymbolAddress((void**)&hid, g_hid);
    cudaGetSymbolAddress((void**)&w2, g_w2);

    const int SMEM1 = STAGES * 3 * ARR_BYTES;   // 122880
    const int SMEM2 = STAGES * 2 * ARR_BYTES;   // 81920
    cudaFuncSetAttribute((const void*)gemm_split<1, 2>,
                         cudaFuncAttributeMaxDynamicSharedMemorySize, SMEM1);
    cudaFuncSetAttribute((const void*)gemm_split<2, 1>,
                         cudaFuncAttributeMaxDynamicSharedMemorySize, SMEM2);

    {
        size_t n4 = (size_t)N1 * K1 / 4;
        conv_w_kernel<<<(unsigned)((n4 + 255) / 256), 256>>>(p1_w, w1, n4);
    }
    {
        size_t n4 = (size_t)N2 * K2 / 4;
        conv_w_kernel<<<(unsigned)((n4 + 255) / 256), 256>>>(p2_w, w2, n4);
    }
    {
        size_t n = (size_t)M_PAD * 256;
        conv_x_kernel<<<(unsigned)((n + 255) / 256), 256>>>(seq, a1hi, a1lo);
    }
    ema_kernel<<<(B_SZ * D_SZ + 255) / 256, 256>>>(seq, beta_raw, a1hi, a1lo);

    // GEMM1 (2-term A): hid = relu(A1 @ p1_w^T + p1_b) -> fp16
    {
        dim3 grid(N1 / BN, M_PAD / BM);
        gemm_split<1, 2><<<grid, 256, SMEM1>>>(a1hi, a1lo, w1, p1_b,
                                               hid, nullptr, N1, K1);
    }
    // GEMM2 (1-term A): x_hat = hid @ p2_w^T + p2_b -> fp32 d_out
    {
        dim3 grid(N2 / BN, M_PAD / BM);
        gemm_split<2, 1><<<grid, 256, SMEM2>>>(hid, nullptr, w2, p2_b,
                                               nullptr, xhat, N2, K2);
    }
    // GEMM3
    {
        dim3 grid(N3 / 64, (M_ROWS + 127) / 128);
        gemm3_kernel<128, 64, 16, 8, 4><<<grid, 256>>>(xhat, W_w, W_b, pi,
                                                       logits, M_ROWS, N3, K3);
    }
}

// round 7
// speedup vs baseline: 5.7700x; 1.6470x over previous
#include <cuda_runtime.h>
#include <cuda_fp16.h>
#include <math.h>
#include <stdint.h>

// ---------------------------------------------------------------------------
// Problem constants
// ---------------------------------------------------------------------------
#define B_SZ 16
#define T_SZ 1024
#define D_SZ 1024
#define E_SZ 64
#define TS   (T_SZ - 1)          // 1023
#define M_ROWS (TS * B_SZ)       // 16368
#define M_PAD  16384
#define K1 2048
#define N1 4096
#define K2 4096
#define N2 1024
#define K3 1024
#define N3 64
#define LOGITS_ELEMS (M_ROWS * E_SZ)

// GEMM tiling
#define BM 128
#define BN 128
#define BK 32                    // fp16 elements per k-chunk (64 bytes/row)
#define STAGES 4
#define ROW_BYTES 80             // 64B data + 16B skew -> conflict-free ldmatrix
#define ARR_BYTES (BM * ROW_BYTES)          // 10240 per array
#define STAGE_BYTES (2 * ARR_BYTES)         // A | B
#define SMEM_TOTAL (STAGES * STAGE_BYTES)   // 81920

// ---------------------------------------------------------------------------
// Device scratch (16B aligned)
// ---------------------------------------------------------------------------
__device__ __align__(16) __half g_a1[(size_t)M_PAD * K1];
__device__ __align__(16) __half g_w1[(size_t)N1 * K1];
__device__ __align__(16) __half g_hid[(size_t)M_PAD * N1];
__device__ __align__(16) __half g_w2[(size_t)N2 * K2];

// ---------------------------------------------------------------------------
// PTX helpers (base-arch sm_80+)
// ---------------------------------------------------------------------------
__device__ __forceinline__ uint32_t smem_u32(const void* p) {
    uint32_t a;
    asm("{ .reg .u64 t; cvta.to.shared.u64 t, %1; cvt.u32.u64 %0, t; }" : "=r"(a) : "l"(p));
    return a;
}

__device__ __forceinline__ void cp_async16(uint32_t dst, const void* src) {
    asm volatile("cp.async.cg.shared.global [%0], [%1], 16;" :: "r"(dst), "l"(src));
}
__device__ __forceinline__ void cp_commit() {
    asm volatile("cp.async.commit_group;" ::: "memory");
}
template <int N>
__device__ __forceinline__ void cp_wait() {
    asm volatile("cp.async.wait_group %0;" :: "n"(N) : "memory");
}

__device__ __forceinline__ void ldsm_x4(uint32_t* r, uint32_t addr) {
    asm volatile("ldmatrix.sync.aligned.m8n8.x4.shared.b16 {%0,%1,%2,%3}, [%4];"
                 : "=r"(r[0]), "=r"(r[1]), "=r"(r[2]), "=r"(r[3]) : "r"(addr));
}

__device__ __forceinline__ void mma_f16(float* d, const uint32_t* a, uint32_t b0, uint32_t b1) {
    asm volatile(
        "mma.sync.aligned.m16n8k16.row.col.f32.f16.f16.f32 "
        "{%0,%1,%2,%3}, {%4,%5,%6,%7}, {%8,%9}, {%0,%1,%2,%3};"
        : "+f"(d[0]), "+f"(d[1]), "+f"(d[2]), "+f"(d[3])
        : "r"(a[0]), "r"(a[1]), "r"(a[2]), "r"(a[3]), "r"(b0), "r"(b1));
}

// ---------------------------------------------------------------------------
// Weight conversion: fp32 -> fp16
// ---------------------------------------------------------------------------
__global__ void conv_w_kernel(const float* __restrict__ in,
                              __half* __restrict__ out, size_t n4) {
    size_t i = (size_t)blockIdx.x * blockDim.x + threadIdx.x;
    if (i >= n4) return;
    float4 v = ((const float4*)in)[i];
    ((ushort4*)out)[i] = make_ushort4(
        __half_as_ushort(__float2half_rn(v.x)), __half_as_ushort(__float2half_rn(v.y)),
        __half_as_ushort(__float2half_rn(v.z)), __half_as_ushort(__float2half_rn(v.w)));
}

// ---------------------------------------------------------------------------
// Build x-half of A1 (k < 1024 only); pad rows zero BOTH halves.  m = t*16+b
// ---------------------------------------------------------------------------
__global__ void conv_x_kernel(const float* __restrict__ seq,
                              __half* __restrict__ a1) {
    size_t i = (size_t)blockIdx.x * blockDim.x + threadIdx.x;  // over M_PAD*256
    if (i >= (size_t)M_PAD * 256) return;
    int m = (int)(i >> 8);
    int k = (int)(i & 255) * 4;
    size_t o = (size_t)m * K1 + k;
    if (m < M_ROWS) {
        int t = m >> 4, b = m & 15;
        float4 v = *(const float4*)(seq + ((size_t)b * T_SZ + t) * D_SZ + k);
        *(ushort4*)(a1 + o) = make_ushort4(
            __half_as_ushort(__float2half_rn(v.x)), __half_as_ushort(__float2half_rn(v.y)),
            __half_as_ushort(__float2half_rn(v.z)), __half_as_ushort(__float2half_rn(v.w)));
    } else {
        ushort4 z = make_ushort4(0, 0, 0, 0);
        *(ushort4*)(a1 + o) = z;           // x half
        *(ushort4*)(a1 + o + D_SZ) = z;    // hs half
    }
}

// ---------------------------------------------------------------------------
// EMA recurrence -> A1 columns [1024,2048) as fp16
// ---------------------------------------------------------------------------
__global__ void ema_kernel(const float* __restrict__ seq,
                           const float* __restrict__ beta_raw,
                           __half* __restrict__ a1) {
    int idx = blockIdx.x * blockDim.x + threadIdx.x;
    if (idx >= B_SZ * D_SZ) return;
    int b = idx / D_SZ, d = idx % D_SZ;
    float beta = 1.0f / (1.0f + expf(-beta_raw[d]));
    float h = 0.0f;
    const float* sp = seq + (size_t)b * T_SZ * D_SZ + d;
    size_t base = (size_t)b * K1 + D_SZ + d;
#pragma unroll 8
    for (int t = 0; t < TS; ++t) {
        h = fmaf(beta, h, sp[(size_t)t * D_SZ]);
        a1[base + (size_t)t * (B_SZ * K1)] = __float2half_rn(h);
    }
}

// ---------------------------------------------------------------------------
// fp16 mma.sync GEMM: D[M_PAD,N] = A @ Wh^T   (fp32 acc)
// EPI 1: relu(acc+bias) -> fp16 out          EPI 2: acc+bias -> fp32 (M_ROWS)
// 256 threads, warps 2(M)x4(N), warp tile 64x32, 4-stage cp.async,
// one __syncthreads per k-chunk.
// ---------------------------------------------------------------------------
template <int EPI>
__global__ void __launch_bounds__(256, 1)
gemm_f16(const __half* __restrict__ A, const __half* __restrict__ Wh,
         const float* __restrict__ bias,
         __half* __restrict__ outH, float* __restrict__ outF, int N, int K) {
    extern __shared__ char smem[];
    const uint32_t sbase = smem_u32(smem);
    const int tid = threadIdx.x;
    const int lane = tid & 31;
    const int wid = tid >> 5;
    const int wm0 = (wid & 1) * 64;
    const int wn0 = (wid >> 1) * 32;
    const int m0 = blockIdx.y * BM;
    const int n0 = blockIdx.x * BN;
    const int NK = K / BK;

    float acc[4][4][4];
#pragma unroll
    for (int a = 0; a < 4; ++a)
#pragma unroll
        for (int b = 0; b < 4; ++b)
#pragma unroll
            for (int c = 0; c < 4; ++c) acc[a][b][c] = 0.0f;

    const int r0s = tid >> 2, c0s = tid & 3;
    const int r1s = (tid + 256) >> 2;

    auto load_stage = [&](int kc) {
        const uint32_t sb = sbase + (uint32_t)(kc % STAGES) * STAGE_BYTES;
        const size_t gcol = (size_t)kc * BK;
#pragma unroll
        for (int q = 0; q < 2; ++q) {
            const int r = q ? r1s : r0s;
            const uint32_t so = (uint32_t)(r * ROW_BYTES + c0s * 16);
            cp_async16(sb + so, A + (size_t)(m0 + r) * K + gcol + c0s * 8);
            cp_async16(sb + ARR_BYTES + so, Wh + (size_t)(n0 + r) * K + gcol + c0s * 8);
        }
        cp_commit();
    };

    load_stage(0);
    load_stage(1);
    load_stage(2);

    const uint32_t lrow = (uint32_t)(lane & 15);
    const uint32_t lcol = (uint32_t)((lane >> 4) * 16);

    for (int kc = 0; kc < NK; ++kc) {
        const int rem = NK - 1 - kc;
        if (rem >= 2) cp_wait<2>();
        else if (rem == 1) cp_wait<1>();
        else cp_wait<0>();
        __syncthreads();
        if (kc + 3 < NK) load_stage(kc + 3);

        const uint32_t sb = sbase + (uint32_t)(kc % STAGES) * STAGE_BYTES;
#pragma unroll
        for (int j = 0; j < 2; ++j) {   // two k16 steps
            const uint32_t colb = (uint32_t)(j * 32) + lcol;
            uint32_t ah[4][4];
#pragma unroll
            for (int mf = 0; mf < 4; ++mf) {
                uint32_t ad = sb + (uint32_t)((wm0 + mf * 16 + lrow) * ROW_BYTES) + colb;
                ldsm_x4(ah[mf], ad);
            }
            uint32_t bh[2][4];
#pragma unroll
            for (int np = 0; np < 2; ++np) {
                uint32_t bd = sb + ARR_BYTES +
                              (uint32_t)((wn0 + np * 16 + lrow) * ROW_BYTES) + colb;
                ldsm_x4(bh[np], bd);
            }
#pragma unroll
            for (int mf = 0; mf < 4; ++mf) {
#pragma unroll
                for (int np = 0; np < 2; ++np) {
                    mma_f16(acc[mf][2 * np],     ah[mf], bh[np][0], bh[np][2]);
                    mma_f16(acc[mf][2 * np + 1], ah[mf], bh[np][1], bh[np][3]);
                }
            }
        }
    }

    // Epilogue
    const int g = lane >> 2;
    const int t2 = (lane & 3) * 2;
#pragma unroll
    for (int mf = 0; mf < 4; ++mf) {
#pragma unroll
        for (int nf = 0; nf < 4; ++nf) {
            const int n = n0 + wn0 + nf * 8 + t2;
            const float2 bv = *(const float2*)(bias + n);
#pragma unroll
            for (int h = 0; h < 2; ++h) {
                const int m = m0 + wm0 + mf * 16 + g + h * 8;
                float v0 = acc[mf][nf][h * 2 + 0] + bv.x;
                float v1 = acc[mf][nf][h * 2 + 1] + bv.y;
                if (EPI == 1) {
                    v0 = fmaxf(v0, 0.0f);
                    v1 = fmaxf(v1, 0.0f);
                    *(ushort2*)(outH + (size_t)m * N + n) =
                        make_ushort2(__half_as_ushort(__float2half_rn(v0)),
                                     __half_as_ushort(__float2half_rn(v1)));
                } else {
                    if (m < M_ROWS)
                        *(float2*)(outF + (size_t)m * N + n) = make_float2(v0, v1);
                }
            }
        }
    }
}

// ---------------------------------------------------------------------------
// GEMM3 (SIMT fp32): logits = (x_hat @ W_w^T + W_b) * pi
// ---------------------------------------------------------------------------
template <int TBM, int TBN, int TBK, int TM, int TN>
__global__ void __launch_bounds__(256)
gemm3_kernel(const float* __restrict__ A, const float* __restrict__ W,
             const float* __restrict__ bias, const float* __restrict__ scale,
             float* __restrict__ C, int Mrows, int N, int K) {
    __shared__ float As[TBK][TBM + 4];
    __shared__ float Ws[TBK][TBN + 4];
    const int tid = threadIdx.x;
    const int m0 = blockIdx.y * TBM;
    const int n0 = blockIdx.x * TBN;
    const int tx = tid % (TBN / TN);
    const int ty = tid / (TBN / TN);

    float acc[TM][TN];
#pragma unroll
    for (int i = 0; i < TM; ++i)
#pragma unroll
        for (int j = 0; j < TN; ++j) acc[i][j] = 0.0f;

    for (int k0 = 0; k0 < K; k0 += TBK) {
#pragma unroll
        for (int i = tid; i < TBM * TBK / 4; i += 256) {
            int row = i / (TBK / 4);
            int c = (i % (TBK / 4)) * 4;
            float4 v = make_float4(0.f, 0.f, 0.f, 0.f);
            if (m0 + row < Mrows)
                v = *(const float4*)(A + (size_t)(m0 + row) * K + k0 + c);
            As[c + 0][row] = v.x; As[c + 1][row] = v.y;
            As[c + 2][row] = v.z; As[c + 3][row] = v.w;
        }
#pragma unroll
        for (int i = tid; i < TBN * TBK / 4; i += 256) {
            int row = i / (TBK / 4);
            int c = (i % (TBK / 4)) * 4;
            float4 v = *(const float4*)(W + (size_t)(n0 + row) * K + k0 + c);
            Ws[c + 0][row] = v.x; Ws[c + 1][row] = v.y;
            Ws[c + 2][row] = v.z; Ws[c + 3][row] = v.w;
        }
        __syncthreads();
#pragma unroll
        for (int k = 0; k < TBK; ++k) {
            float ar[TM], br[TN];
#pragma unroll
            for (int i = 0; i < TM; ++i) ar[i] = As[k][ty * TM + i];
#pragma unroll
            for (int j = 0; j < TN; ++j) br[j] = Ws[k][tx * TN + j];
#pragma unroll
            for (int i = 0; i < TM; ++i)
#pragma unroll
                for (int j = 0; j < TN; ++j)
                    acc[i][j] = fmaf(ar[i], br[j], acc[i][j]);
        }
        __syncthreads();
    }
#pragma unroll
    for (int i = 0; i < TM; ++i) {
        int row = m0 + ty * TM + i;
        if (row >= Mrows) continue;
#pragma unroll
        for (int j = 0; j < TN; ++j) {
            int col = n0 + tx * TN + j;
            C[(size_t)row * N + col] = (acc[i][j] + bias[col]) * scale[col];
        }
    }
}

// ---------------------------------------------------------------------------
// Launch
// ---------------------------------------------------------------------------
extern "C" void kernel_launch(void* const* d_in, const int* in_sizes, int n_in,
                              void* d_out, int out_size) {
    const float* seq      = (const float*)d_in[0];
    const float* pi       = (const float*)d_in[1];
    const float* beta_raw = (const float*)d_in[2];
    const float* p1_w     = (const float*)d_in[3];
    const float* p1_b     = (const float*)d_in[4];
    const float* p2_w     = (const float*)d_in[5];
    const float* p2_b     = (const float*)d_in[6];
    const float* W_w      = (const float*)d_in[7];
    const float* W_b      = (const float*)d_in[8];

    float* logits = (float*)d_out;
    float* xhat   = (float*)d_out + LOGITS_ELEMS;

    __half *a1, *w1, *hid, *w2;
    cudaGetSymbolAddress((void**)&a1, g_a1);
    cudaGetSymbolAddress((void**)&w1, g_w1);
    cudaGetSymbolAddress((void**)&hid, g_hid);
    cudaGetSymbolAddress((void**)&w2, g_w2);

    cudaFuncSetAttribute((const void*)gemm_f16<1>,
                         cudaFuncAttributeMaxDynamicSharedMemorySize, SMEM_TOTAL);
    cudaFuncSetAttribute((const void*)gemm_f16<2>,
                         cudaFuncAttributeMaxDynamicSharedMemorySize, SMEM_TOTAL);

    {
        size_t n4 = (size_t)N1 * K1 / 4;
        conv_w_kernel<<<(unsigned)((n4 + 255) / 256), 256>>>(p1_w, w1, n4);
    }
    {
        size_t n4 = (size_t)N2 * K2 / 4;
        conv_w_kernel<<<(unsigned)((n4 + 255) / 256), 256>>>(p2_w, w2, n4);
    }
    {
        size_t n = (size_t)M_PAD * 256;
        conv_x_kernel<<<(unsigned)((n + 255) / 256), 256>>>(seq, a1);
    }
    ema_kernel<<<(B_SZ * D_SZ + 255) / 256, 256>>>(seq, beta_raw, a1);

    // GEMM1: hid = relu(A1 @ p1_w^T + p1_b) -> fp16
    {
        dim3 grid(N1 / BN, M_PAD / BM);
        gemm_f16<1><<<grid, 256, SMEM_TOTAL>>>(a1, w1, p1_b, hid, nullptr, N1, K1);
    }
    // GEMM2: x_hat = hid @ p2_w^T + p2_b -> fp32 d_out
    {
        dim3 grid(N2 / BN, M_PAD / BM);
        gemm_f16<2><<<grid, 256, SMEM_TOTAL>>>(hid, w2, p2_b, nullptr, xhat, N2, K2);
    }
    // GEMM3
    {
        dim3 grid(N3 / 64, (M_ROWS + 127) / 128);
        gemm3_kernel<128, 64, 16, 8, 4><<<grid, 256>>>(xhat, W_w, W_b, pi,
                                                       logits, M_ROWS, N3, K3);
    }
}

// round 8
// speedup vs baseline: 6.3083x; 1.0933x over previous
#include <cuda_runtime.h>
#include <cuda_fp16.h>
#include <math.h>
#include <stdint.h>

// ---------------------------------------------------------------------------
// Problem constants
// ---------------------------------------------------------------------------
#define B_SZ 16
#define T_SZ 1024
#define D_SZ 1024
#define E_SZ 64
#define TS   (T_SZ - 1)          // 1023
#define M_ROWS (TS * B_SZ)       // 16368
#define M_PAD  16384
#define K1 2048
#define N1 4096
#define K2 4096
#define N2 1024
#define K3 1024
#define N3 64
#define LOGITS_ELEMS (M_ROWS * E_SZ)

// GEMM tiling
#define BM 128
#define BN 128
#define BK 32                    // fp16 elements per k-chunk (64 bytes/row)
#define STAGES 4
#define ROW_BYTES 80             // 64B data + 16B skew -> conflict-free ldmatrix
#define ARR_BYTES (BM * ROW_BYTES)          // 10240
#define STAGE_BYTES (2 * ARR_BYTES)
#define SMEM_TOTAL (STAGES * STAGE_BYTES)   // 81920

// GEMM3 tiling (BM=128, N=64)
#define G3_B_BYTES (64 * ROW_BYTES)              // 5120
#define G3_STAGE (ARR_BYTES + G3_B_BYTES)        // 15360
#define G3_SMEM (STAGES * G3_STAGE)              // 61440

// ---------------------------------------------------------------------------
// Device scratch (16B aligned)
// ---------------------------------------------------------------------------
__device__ __align__(16) __half g_a1[(size_t)M_PAD * K1];
__device__ __align__(16) __half g_w1[(size_t)N1 * K1];
__device__ __align__(16) __half g_hid[(size_t)M_PAD * N1];
__device__ __align__(16) __half g_w2[(size_t)N2 * K2];
__device__ __align__(16) __half g_xh16[(size_t)M_PAD * N2];
__device__ __align__(16) __half g_wpi[(size_t)N3 * K3];
__device__ __align__(16) float  g_bpi[N3];

// ---------------------------------------------------------------------------
// PTX helpers (base-arch sm_80+)
// ---------------------------------------------------------------------------
__device__ __forceinline__ uint32_t smem_u32(const void* p) {
    uint32_t a;
    asm("{ .reg .u64 t; cvta.to.shared.u64 t, %1; cvt.u32.u64 %0, t; }" : "=r"(a) : "l"(p));
    return a;
}
__device__ __forceinline__ void cp_async16(uint32_t dst, const void* src) {
    asm volatile("cp.async.cg.shared.global [%0], [%1], 16;" :: "r"(dst), "l"(src));
}
__device__ __forceinline__ void cp_commit() {
    asm volatile("cp.async.commit_group;" ::: "memory");
}
template <int N>
__device__ __forceinline__ void cp_wait() {
    asm volatile("cp.async.wait_group %0;" :: "n"(N) : "memory");
}
__device__ __forceinline__ void ldsm_x4(uint32_t* r, uint32_t addr) {
    asm volatile("ldmatrix.sync.aligned.m8n8.x4.shared.b16 {%0,%1,%2,%3}, [%4];"
                 : "=r"(r[0]), "=r"(r[1]), "=r"(r[2]), "=r"(r[3]) : "r"(addr));
}
__device__ __forceinline__ void mma_f16(float* d, const uint32_t* a, uint32_t b0, uint32_t b1) {
    asm volatile(
        "mma.sync.aligned.m16n8k16.row.col.f32.f16.f16.f32 "
        "{%0,%1,%2,%3}, {%4,%5,%6,%7}, {%8,%9}, {%0,%1,%2,%3};"
        : "+f"(d[0]), "+f"(d[1]), "+f"(d[2]), "+f"(d[3])
        : "r"(a[0]), "r"(a[1]), "r"(a[2]), "r"(a[3]), "r"(b0), "r"(b1));
}

// ---------------------------------------------------------------------------
// Weight conversion: fp32 -> fp16
// ---------------------------------------------------------------------------
__global__ void conv_w_kernel(const float* __restrict__ in,
                              __half* __restrict__ out, size_t n4) {
    size_t i = (size_t)blockIdx.x * blockDim.x + threadIdx.x;
    if (i >= n4) return;
    float4 v = ((const float4*)in)[i];
    ((ushort4*)out)[i] = make_ushort4(
        __half_as_ushort(__float2half_rn(v.x)), __half_as_ushort(__float2half_rn(v.y)),
        __half_as_ushort(__float2half_rn(v.z)), __half_as_ushort(__float2half_rn(v.w)));
}

// Router weights: Wpi = fp16(pi[e] * W_w[e,:]),  bpi = W_b * pi
__global__ void conv_wpi_kernel(const float* __restrict__ W, const float* __restrict__ pi,
                                const float* __restrict__ Wb,
                                __half* __restrict__ Wpi, float* __restrict__ bpi) {
    int i = blockIdx.x * blockDim.x + threadIdx.x;     // over 64*1024/4 = 16384
    if (i < N3 * K3 / 4) {
        float4 v = ((const float4*)W)[i];
        float p = pi[i >> 8];                          // e = i / (1024/4)
        ((ushort4*)Wpi)[i] = make_ushort4(
            __half_as_ushort(__float2half_rn(v.x * p)), __half_as_ushort(__float2half_rn(v.y * p)),
            __half_as_ushort(__float2half_rn(v.z * p)), __half_as_ushort(__float2half_rn(v.w * p)));
    }
    if (i < N3) bpi[i] = Wb[i] * pi[i];
}

// Zero pad rows [M_ROWS, M_PAD) of A1 (both halves)
__global__ void pad_zero_kernel(__half* __restrict__ a1) {
    int i = blockIdx.x * blockDim.x + threadIdx.x;     // over 16*2048/8 = 4096
    if (i >= (M_PAD - M_ROWS) * K1 / 8) return;
    ((uint4*)(a1 + (size_t)M_ROWS * K1))[i] = make_uint4(0, 0, 0, 0);
}

// ---------------------------------------------------------------------------
// Fused EMA (chunked parallel scan) + x-half conversion.
// Block: 256 threads = 16 chunks x 16 channels. Grid: 16 (b) * 64 (dgroup).
// Writes BOTH A1 halves for all rows m = t*16+b.
// ---------------------------------------------------------------------------
__global__ void __launch_bounds__(256)
ema_fused_kernel(const float* __restrict__ seq, const float* __restrict__ beta_raw,
                 __half* __restrict__ a1) {
    __shared__ float sL[16][16];
    __shared__ float sBP[16][16];
    const int tid = threadIdx.x;
    const int dl = tid & 15;           // channel lane within block
    const int c = tid >> 4;            // chunk index 0..15
    const int b = blockIdx.x >> 6;     // batch 0..15
    const int d = ((blockIdx.x & 63) << 4) + dl;
    const float beta = 1.0f / (1.0f + expf(-beta_raw[d]));
    const int t0 = c * 64;
    const int t1 = (t0 + 64 < TS) ? t0 + 64 : TS;
    const float* sp = seq + (size_t)b * T_SZ * D_SZ + d;

    // Phase 1: local EMA of this chunk (zero init), plus beta^len
    float L = 0.0f, bp = 1.0f;
#pragma unroll 4
    for (int t = t0; t < t1; ++t) {
        L = fmaf(beta, L, sp[(size_t)t * D_SZ]);
        bp *= beta;
    }
    sL[c][dl] = L;
    sBP[c][dl] = bp;
    __syncthreads();

    // Phase 2: carry into this chunk = state after chunks 0..c-1
    float H = 0.0f;
    for (int j = 0; j < c; ++j)
        H = fmaf(sBP[j][dl], H, sL[j][dl]);

    // Phase 3: replay chunk with carry; emit x (fp16) and h (fp16)
    float h = H;
#pragma unroll 4
    for (int t = t0; t < t1; ++t) {
        float x = sp[(size_t)t * D_SZ];
        h = fmaf(beta, h, x);
        const size_t m = (size_t)t * B_SZ + b;
        a1[m * K1 + d] = __float2half_rn(x);
        a1[m * K1 + D_SZ + d] = __float2half_rn(h);
    }
}

// ---------------------------------------------------------------------------
// fp16 mma.sync GEMM: D[M_PAD,N] = A @ Wh^T   (fp32 acc)
// EPI 1: relu(acc+bias) -> fp16 outH
// EPI 2: acc+bias -> fp32 outF (m<M_ROWS) AND fp16 outH (all rows)
// ---------------------------------------------------------------------------
template <int EPI>
__global__ void __launch_bounds__(256, 1)
gemm_f16(const __half* __restrict__ A, const __half* __restrict__ Wh,
         const float* __restrict__ bias,
         __half* __restrict__ outH, float* __restrict__ outF, int N, int K) {
    extern __shared__ char smem[];
    const uint32_t sbase = smem_u32(smem);
    const int tid = threadIdx.x;
    const int lane = tid & 31;
    const int wid = tid >> 5;
    const int wm0 = (wid & 1) * 64;
    const int wn0 = (wid >> 1) * 32;
    const int m0 = blockIdx.y * BM;
    const int n0 = blockIdx.x * BN;
    const int NK = K / BK;

    float acc[4][4][4];
#pragma unroll
    for (int a = 0; a < 4; ++a)
#pragma unroll
        for (int b = 0; b < 4; ++b)
#pragma unroll
            for (int c = 0; c < 4; ++c) acc[a][b][c] = 0.0f;

    const int r0s = tid >> 2, c0s = tid & 3;
    const int r1s = (tid + 256) >> 2;

    auto load_stage = [&](int kc) {
        const uint32_t sb = sbase + (uint32_t)(kc % STAGES) * STAGE_BYTES;
        const size_t gcol = (size_t)kc * BK;
#pragma unroll
        for (int q = 0; q < 2; ++q) {
            const int r = q ? r1s : r0s;
            const uint32_t so = (uint32_t)(r * ROW_BYTES + c0s * 16);
            cp_async16(sb + so, A + (size_t)(m0 + r) * K + gcol + c0s * 8);
            cp_async16(sb + ARR_BYTES + so, Wh + (size_t)(n0 + r) * K + gcol + c0s * 8);
        }
        cp_commit();
    };

    load_stage(0);
    load_stage(1);
    load_stage(2);

    const uint32_t lrow = (uint32_t)(lane & 15);
    const uint32_t lcol = (uint32_t)((lane >> 4) * 16);

    for (int kc = 0; kc < NK; ++kc) {
        const int rem = NK - 1 - kc;
        if (rem >= 2) cp_wait<2>();
        else if (rem == 1) cp_wait<1>();
        else cp_wait<0>();
        __syncthreads();
        if (kc + 3 < NK) load_stage(kc + 3);

        const uint32_t sb = sbase + (uint32_t)(kc % STAGES) * STAGE_BYTES;
#pragma unroll
        for (int j = 0; j < 2; ++j) {
            const uint32_t colb = (uint32_t)(j * 32) + lcol;
            uint32_t ah[4][4];
#pragma unroll
            for (int mf = 0; mf < 4; ++mf)
                ldsm_x4(ah[mf], sb + (uint32_t)((wm0 + mf * 16 + lrow) * ROW_BYTES) + colb);
            uint32_t bh[2][4];
#pragma unroll
            for (int np = 0; np < 2; ++np)
                ldsm_x4(bh[np], sb + ARR_BYTES +
                                (uint32_t)((wn0 + np * 16 + lrow) * ROW_BYTES) + colb);
#pragma unroll
            for (int mf = 0; mf < 4; ++mf) {
#pragma unroll
                for (int np = 0; np < 2; ++np) {
                    mma_f16(acc[mf][2 * np],     ah[mf], bh[np][0], bh[np][2]);
                    mma_f16(acc[mf][2 * np + 1], ah[mf], bh[np][1], bh[np][3]);
                }
            }
        }
    }

    const int g = lane >> 2;
    const int t2 = (lane & 3) * 2;
#pragma unroll
    for (int mf = 0; mf < 4; ++mf) {
#pragma unroll
        for (int nf = 0; nf < 4; ++nf) {
            const int n = n0 + wn0 + nf * 8 + t2;
            const float2 bv = *(const float2*)(bias + n);
#pragma unroll
            for (int h = 0; h < 2; ++h) {
                const int m = m0 + wm0 + mf * 16 + g + h * 8;
                float v0 = acc[mf][nf][h * 2 + 0] + bv.x;
                float v1 = acc[mf][nf][h * 2 + 1] + bv.y;
                if (EPI == 1) {
                    v0 = fmaxf(v0, 0.0f);
                    v1 = fmaxf(v1, 0.0f);
                    *(ushort2*)(outH + (size_t)m * N + n) =
                        make_ushort2(__half_as_ushort(__float2half_rn(v0)),
                                     __half_as_ushort(__float2half_rn(v1)));
                } else {
                    *(ushort2*)(outH + (size_t)m * N + n) =
                        make_ushort2(__half_as_ushort(__float2half_rn(v0)),
                                     __half_as_ushort(__float2half_rn(v1)));
                    if (m < M_ROWS)
                        *(float2*)(outF + (size_t)m * N + n) = make_float2(v0, v1);
                }
            }
        }
    }
}

// ---------------------------------------------------------------------------
// GEMM3 (mma fp16): logits[M,64] = xh16 @ Wpi^T + bpi   (fp32 out, m<M_ROWS)
// 8 warps: 4(M) x 2(N), warp tile 32x32. K=1024.
// ---------------------------------------------------------------------------
__global__ void __launch_bounds__(256, 1)
gemm3_mma(const __half* __restrict__ A, const __half* __restrict__ Wpi,
          const float* __restrict__ bpi, float* __restrict__ C) {
    const int K = K3;
    extern __shared__ char smem[];
    const uint32_t sbase = smem_u32(smem);
    const int tid = threadIdx.x;
    const int lane = tid & 31;
    const int wid = tid >> 5;
    const int wm0 = (wid & 3) * 32;
    const int wn0 = (wid >> 2) * 32;
    const int m0 = blockIdx.x * BM;
    const int NK = K / BK;   // 32

    float acc[2][4][4];
#pragma unroll
    for (int a = 0; a < 2; ++a)
#pragma unroll
        for (int b = 0; b < 4; ++b)
#pragma unroll
            for (int c = 0; c < 4; ++c) acc[a][b][c] = 0.0f;

    auto load_stage = [&](int kc) {
        const uint32_t sb = sbase + (uint32_t)(kc % STAGES) * G3_STAGE;
        const size_t gcol = (size_t)kc * BK;
        // A: 512 slots (2 per thread)
#pragma unroll
        for (int q = 0; q < 2; ++q) {
            const int s = tid + q * 256;
            const int r = s >> 2, ch = s & 3;
            cp_async16(sb + (uint32_t)(r * ROW_BYTES + ch * 16),
                       A + (size_t)(m0 + r) * K + gcol + ch * 8);
        }
        // B: 256 slots (1 per thread)
        {
            const int r = tid >> 2, ch = tid & 3;
            cp_async16(sb + ARR_BYTES + (uint32_t)(r * ROW_BYTES + ch * 16),
                       Wpi + (size_t)r * K + gcol + ch * 8);
        }
        cp_commit();
    };

    load_stage(0);
    load_stage(1);
    load_stage(2);

    const uint32_t lrow = (uint32_t)(lane & 15);
    const uint32_t lcol = (uint32_t)((lane >> 4) * 16);

    for (int kc = 0; kc < NK; ++kc) {
        const int rem = NK - 1 - kc;
        if (rem >= 2) cp_wait<2>();
        else if (rem == 1) cp_wait<1>();
        else cp_wait<0>();
        __syncthreads();
        if (kc + 3 < NK) load_stage(kc + 3);

        const uint32_t sb = sbase + (uint32_t)(kc % STAGES) * G3_STAGE;
#pragma unroll
        for (int j = 0; j < 2; ++j) {
            const uint32_t colb = (uint32_t)(j * 32) + lcol;
            uint32_t ah[2][4];
#pragma unroll
            for (int mf = 0; mf < 2; ++mf)
                ldsm_x4(ah[mf], sb + (uint32_t)((wm0 + mf * 16 + lrow) * ROW_BYTES) + colb);
            uint32_t bh[2][4];
#pragma unroll
            for (int np = 0; np < 2; ++np)
                ldsm_x4(bh[np], sb + ARR_BYTES +
                                (uint32_t)((wn0 + np * 16 + lrow) * ROW_BYTES) + colb);
#pragma unroll
            for (int mf = 0; mf < 2; ++mf) {
#pragma unroll
                for (int np = 0; np < 2; ++np) {
                    mma_f16(acc[mf][2 * np],     ah[mf], bh[np][0], bh[np][2]);
                    mma_f16(acc[mf][2 * np + 1], ah[mf], bh[np][1], bh[np][3]);
                }
            }
        }
    }

    const int g = lane >> 2;
    const int t2 = (lane & 3) * 2;
#pragma unroll
    for (int mf = 0; mf < 2; ++mf) {
#pragma unroll
        for (int nf = 0; nf < 4; ++nf) {
            const int n = wn0 + nf * 8 + t2;
            const float2 bv = *(const float2*)(bpi + n);
#pragma unroll
            for (int h = 0; h < 2; ++h) {
                const int m = m0 + wm0 + mf * 16 + g + h * 8;
                if (m < M_ROWS) {
                    float v0 = acc[mf][nf][h * 2 + 0] + bv.x;
                    float v1 = acc[mf][nf][h * 2 + 1] + bv.y;
                    *(float2*)(C + (size_t)m * N3 + n) = make_float2(v0, v1);
                }
            }
        }
    }
}

// ---------------------------------------------------------------------------
// Launch
// ---------------------------------------------------------------------------
extern "C" void kernel_launch(void* const* d_in, const int* in_sizes, int n_in,
                              void* d_out, int out_size) {
    const float* seq      = (const float*)d_in[0];
    const float* pi       = (const float*)d_in[1];
    const float* beta_raw = (const float*)d_in[2];
    const float* p1_w     = (const float*)d_in[3];
    const float* p1_b     = (const float*)d_in[4];
    const float* p2_w     = (const float*)d_in[5];
    const float* p2_b     = (const float*)d_in[6];
    const float* W_w      = (const float*)d_in[7];
    const float* W_b      = (const float*)d_in[8];

    float* logits = (float*)d_out;
    float* xhat   = (float*)d_out + LOGITS_ELEMS;

    __half *a1, *w1, *hid, *w2, *xh16, *wpi;
    float* bpi;
    cudaGetSymbolAddress((void**)&a1, g_a1);
    cudaGetSymbolAddress((void**)&w1, g_w1);
    cudaGetSymbolAddress((void**)&hid, g_hid);
    cudaGetSymbolAddress((void**)&w2, g_w2);
    cudaGetSymbolAddress((void**)&xh16, g_xh16);
    cudaGetSymbolAddress((void**)&wpi, g_wpi);
    cudaGetSymbolAddress((void**)&bpi, g_bpi);

    cudaFuncSetAttribute((const void*)gemm_f16<1>,
                         cudaFuncAttributeMaxDynamicSharedMemorySize, SMEM_TOTAL);
    cudaFuncSetAttribute((const void*)gemm_f16<2>,
                         cudaFuncAttributeMaxDynamicSharedMemorySize, SMEM_TOTAL);
    cudaFuncSetAttribute((const void*)gemm3_mma,
                         cudaFuncAttributeMaxDynamicSharedMemorySize, G3_SMEM);

    // Prep
    {
        size_t n4 = (size_t)N1 * K1 / 4;
        conv_w_kernel<<<(unsigned)((n4 + 255) / 256), 256>>>(p1_w, w1, n4);
    }
    {
        size_t n4 = (size_t)N2 * K2 / 4;
        conv_w_kernel<<<(unsigned)((n4 + 255) / 256), 256>>>(p2_w, w2, n4);
    }
    conv_wpi_kernel<<<(N3 * K3 / 4 + 255) / 256, 256>>>(W_w, pi, W_b, wpi, bpi);
    pad_zero_kernel<<<((M_PAD - M_ROWS) * K1 / 8 + 255) / 256, 256>>>(a1);
    ema_fused_kernel<<<B_SZ * 64, 256>>>(seq, beta_raw, a1);

    // GEMM1: hid = relu(A1 @ p1_w^T + p1_b) -> fp16
    {
        dim3 grid(N1 / BN, M_PAD / BM);
        gemm_f16<1><<<grid, 256, SMEM_TOTAL>>>(a1, w1, p1_b, hid, nullptr, N1, K1);
    }
    // GEMM2: x_hat = hid @ p2_w^T + p2_b -> fp32 d_out + fp16 scratch
    {
        dim3 grid(N2 / BN, M_PAD / BM);
        gemm_f16<2><<<grid, 256, SMEM_TOTAL>>>(hid, w2, p2_b, xh16, xhat, N2, K2);
    }
    // GEMM3: logits = xh16 @ Wpi^T + bpi
    gemm3_mma<<<M_PAD / BM, 256, G3_SMEM>>>(xh16, wpi, bpi, logits);
}